// round 10
// baseline (speedup 1.0000x reference)
#include <cuda_runtime.h>
#include <cuda_bf16.h>
#include <cfloat>
#include <cstdint>

// ---------------------------------------------------------------------------
// K-means: X [m,128] fp32, centroids_init [128,128] fp32, K=128, 15 iters,
// tol=1e-4. Assignment via bf16-split tensor-core GEMM (round-8 structure)
// with in-block fp64 near-tie refinement AND fused segment accumulation:
// each assign block writes a deterministic fp32 partial (its own 128 points,
// exact X reads). update_a merges 782 partials in fp64.
// ---------------------------------------------------------------------------

#define KCLUST 128
#define NDIM   128
#define MAXIT  15
#define MAX_M  100352
#define MAXBLK 784            // ceil(MAX_M / 128)
#define TAU 4e-3f
#define APITCH 72             // bf16 pitch for 64-col smem tiles

__device__ float  g_cent[KCLUST * NDIM];
__device__ float  g_cent_new[KCLUST * NDIM];
__device__ float  g_csqf[KCLUST];
__device__ float  g_part[MAXBLK][KCLUST * NDIM];
__device__ int    g_counts[KCLUST];
__device__ int    g_clusters[MAX_M];
__device__ float  g_xsq[MAX_M];
__device__ int    g_conv[MAXIT + 1];
__device__ int    g_done;

__device__ __nv_bfloat16 g_xhi[MAX_M * NDIM];
__device__ __nv_bfloat16 g_xlo[MAX_M * NDIM];
__device__ __nv_bfloat16 g_chi[KCLUST * NDIM];
__device__ __nv_bfloat16 g_clo[KCLUST * NDIM];

// ---------------------------------------------------------------------------
__global__ void init_kernel(const float* __restrict__ c0) {
    int b = blockIdx.x, t = threadIdx.x;
    if (b < 128) {
        int idx = b * 128 + t;
        float v = c0[idx];
        g_cent[idx] = v;
        __nv_bfloat16 hi = __float2bfloat16(v);
        g_chi[idx] = hi;
        g_clo[idx] = __float2bfloat16(v - __bfloat162float(hi));
        __shared__ double rb[128];
        rb[t] = (double)v * (double)v;
        __syncthreads();
        #pragma unroll
        for (int o = 64; o; o >>= 1) {
            if (t < o) rb[t] += rb[t + o];
            __syncthreads();
        }
        if (t == 0) g_csqf[b] = (float)rb[0];
    } else {
        if (t < KCLUST) g_counts[t] = 0;
        if (t < MAXIT + 1) g_conv[t] = 0;
        if (t == 0) g_done = 0;
    }
}

// ---------------------------------------------------------------------------
// One-time: fused x_sq (fp64->fp32) + bf16 split of X (+ zero padded rows).
// ---------------------------------------------------------------------------
__global__ void __launch_bounds__(256)
xprep_kernel(const float* __restrict__ X, int m) {
    int row = blockIdx.x * 8 + (threadIdx.x >> 5);
    int lane = threadIdx.x & 31;
    if (row >= MAX_M) return;
    __nv_bfloat162* hip = (__nv_bfloat162*)(g_xhi + (size_t)row * NDIM + lane * 4);
    __nv_bfloat162* lop = (__nv_bfloat162*)(g_xlo + (size_t)row * NDIM + lane * 4);
    if (row < m) {
        float4 v = *reinterpret_cast<const float4*>(&X[(size_t)row * NDIM + lane * 4]);
        float f[4] = {v.x, v.y, v.z, v.w};
        __nv_bfloat16 h[4], l[4];
        #pragma unroll
        for (int j = 0; j < 4; ++j) {
            h[j] = __float2bfloat16(f[j]);
            l[j] = __float2bfloat16(f[j] - __bfloat162float(h[j]));
        }
        hip[0] = __nv_bfloat162(h[0], h[1]);
        hip[1] = __nv_bfloat162(h[2], h[3]);
        lop[0] = __nv_bfloat162(l[0], l[1]);
        lop[1] = __nv_bfloat162(l[2], l[3]);
        double s = (double)v.x * v.x + (double)v.y * v.y +
                   (double)v.z * v.z + (double)v.w * v.w;
        #pragma unroll
        for (int o = 16; o; o >>= 1) s += __shfl_xor_sync(0xFFFFFFFFu, s, o);
        if (lane == 0) g_xsq[row] = (float)s;
    } else {
        __nv_bfloat162 z(__float2bfloat16(0.0f), __float2bfloat16(0.0f));
        hip[0] = z; hip[1] = z; lop[0] = z; lop[1] = z;
    }
}

// ---------------------------------------------------------------------------
// Assignment + fused accumulation.
// ---------------------------------------------------------------------------
#define LDSM_X4(r0, r1, r2, r3, addr) \
    asm volatile("ldmatrix.sync.aligned.m8n8.x4.shared.b16 {%0,%1,%2,%3}, [%4];" \
        : "=r"(r0), "=r"(r1), "=r"(r2), "=r"(r3) : "r"(addr))

#define MMA16816(d, a, b0, b1) \
    asm volatile("mma.sync.aligned.m16n8k16.row.col.f32.bf16.bf16.f32 " \
        "{%0,%1,%2,%3},{%4,%5,%6,%7},{%8,%9},{%0,%1,%2,%3};" \
        : "+f"(d[0]), "+f"(d[1]), "+f"(d[2]), "+f"(d[3]) \
        : "r"(a[0]), "r"(a[1]), "r"(a[2]), "r"(a[3]), "r"(b0), "r"(b1))

#define TILE_B (128 * APITCH)
#define TILE_BYTES (TILE_B * 2)
#define ASSIGN_TC_SMEM (6 * TILE_BYTES + 1024)

__global__ void __launch_bounds__(256, 2)
assign_tc_kernel(const float* __restrict__ X, int m) {
    if (*(volatile int*)&g_done) return;

    extern __shared__ char sm8[];
    __nv_bfloat16* Cs = (__nv_bfloat16*)sm8;         // 4 centroid chunks
    __nv_bfloat16* As = Cs + 4 * TILE_B;             // 2 A buffers
    float* scs = (float*)(As + 2 * TILE_B);
    float* sxq = scs + 128;
    float* redD = (float*)sm8;                       // overlays Cs post-GEMM
    int*   redI = (int*)(sm8 + 2048);
    float* redS = (float*)(sm8 + 4096);
    float* sums = (float*)(sm8 + 8192);              // 64KB overlay (in Cs)

    __shared__ int   s_nf;
    __shared__ int   s_fl[128];
    __shared__ int   s_cid[128];
    __shared__ float sD[128];
    __shared__ int   sI[128];

    const int tid = threadIdx.x;
    const int lane = tid & 31;
    const int wid = tid >> 5;
    const int wm = wid & 3;
    const int wn = wid >> 2;
    const int p0 = blockIdx.x * 128;

    if (tid == 0) s_nf = 0;
    if (tid < 128) {
        scs[tid] = g_csqf[tid];
        int p = p0 + tid;
        sxq[tid] = (p < m) ? g_xsq[p] : 0.0f;
    }

    // Load 4 centroid chunks: {chi kc0, chi kc64, clo kc0, clo kc64}.
    #pragma unroll
    for (int ch = 0; ch < 4; ++ch) {
        const __nv_bfloat16* Bp = (ch < 2) ? g_chi : g_clo;
        int kc = (ch & 1) * 64;
        #pragma unroll
        for (int i = 0; i < 4; ++i) {
            int lin = tid + i * 256;
            int row = lin >> 3, c8 = lin & 7;
            uint4 vb = *(const uint4*)(Bp + row * 128 + kc + c8 * 8);
            *(uint4*)(Cs + ch * TILE_B + row * APITCH + c8 * 8) = vb;
        }
    }

    uint4 nxt[4];
    {
        #pragma unroll
        for (int i = 0; i < 4; ++i) {
            int lin = tid + i * 256;
            int row = lin >> 3, c8 = lin & 7;
            nxt[i] = *(const uint4*)(g_xhi + (size_t)(p0 + row) * 128 + c8 * 8);
        }
        #pragma unroll
        for (int i = 0; i < 4; ++i) {
            int lin = tid + i * 256;
            int row = lin >> 3, c8 = lin & 7;
            *(uint4*)(As + row * APITCH + c8 * 8) = nxt[i];
        }
    }
    __syncthreads();

    const int q = lane >> 3;
    const int r = lane & 7;
    uint32_t asBase = (uint32_t)__cvta_generic_to_shared(As);
    uint32_t csBase = (uint32_t)__cvta_generic_to_shared(Cs);
    uint32_t aoff[2];
    #pragma unroll
    for (int mi = 0; mi < 2; ++mi)
        aoff[mi] = asBase +
            (uint32_t)(((wm * 32 + mi * 16 + (q & 1) * 8 + r) * APITCH + (q >> 1) * 8) * 2);
    uint32_t boff[4];
    #pragma unroll
    for (int nip = 0; nip < 4; ++nip)
        boff[nip] = csBase +
            (uint32_t)(((wn * 64 + nip * 16 + (q >> 1) * 8 + r) * APITCH + (q & 1) * 8) * 2);

    float acc[2][8][4];
    #pragma unroll
    for (int mi = 0; mi < 2; ++mi)
        #pragma unroll
        for (int ni = 0; ni < 8; ++ni)
            #pragma unroll
            for (int u = 0; u < 4; ++u) acc[mi][ni][u] = 0.0f;

    #pragma unroll 1
    for (int s = 0; s < 4; ++s) {
        if (s < 3) {
            const __nv_bfloat16* Ap = (s + 1 < 2) ? g_xhi : g_xlo;
            int kc = ((s + 1) & 1) * 64;
            #pragma unroll
            for (int i = 0; i < 4; ++i) {
                int lin = tid + i * 256;
                int row = lin >> 3, c8 = lin & 7;
                nxt[i] = *(const uint4*)(Ap + (size_t)(p0 + row) * 128 + kc + c8 * 8);
            }
        }

        const uint32_t abuf = (uint32_t)(s & 1) * TILE_BYTES;
        const uint32_t hiB = (uint32_t)(s & 1) * TILE_BYTES;
        const uint32_t loB = (uint32_t)(2 + (s & 1)) * TILE_BYTES;
        const bool doLo = (s < 2);

        #pragma unroll
        for (int ks = 0; ks < 4; ++ks) {
            uint32_t a[2][4];
            #pragma unroll
            for (int mi = 0; mi < 2; ++mi)
                LDSM_X4(a[mi][0], a[mi][1], a[mi][2], a[mi][3],
                        aoff[mi] + abuf + ks * 32);
            uint32_t b[4][4];
            #pragma unroll
            for (int nip = 0; nip < 4; ++nip)
                LDSM_X4(b[nip][0], b[nip][1], b[nip][2], b[nip][3],
                        boff[nip] + hiB + ks * 32);
            #pragma unroll
            for (int mi = 0; mi < 2; ++mi)
                #pragma unroll
                for (int nip = 0; nip < 4; ++nip) {
                    MMA16816(acc[mi][nip * 2 + 0], a[mi], b[nip][0], b[nip][1]);
                    MMA16816(acc[mi][nip * 2 + 1], a[mi], b[nip][2], b[nip][3]);
                }
            if (doLo) {
                #pragma unroll
                for (int nip = 0; nip < 4; ++nip)
                    LDSM_X4(b[nip][0], b[nip][1], b[nip][2], b[nip][3],
                            boff[nip] + loB + ks * 32);
                #pragma unroll
                for (int mi = 0; mi < 2; ++mi)
                    #pragma unroll
                    for (int nip = 0; nip < 4; ++nip) {
                        MMA16816(acc[mi][nip * 2 + 0], a[mi], b[nip][0], b[nip][1]);
                        MMA16816(acc[mi][nip * 2 + 1], a[mi], b[nip][2], b[nip][3]);
                    }
            }
        }

        if (s < 3) {
            #pragma unroll
            for (int i = 0; i < 4; ++i) {
                int lin = tid + i * 256;
                int row = lin >> 3, c8 = lin & 7;
                *(uint4*)(As + ((s + 1) & 1) * TILE_B + row * APITCH + c8 * 8) = nxt[i];
            }
        }
        __syncthreads();
    }

    // Epilogue: d2 + best/second-best per point.
    const int r0 = lane >> 2;
    const int c0 = (lane & 3) * 2;
    float bd[4], sd[4]; int bi[4];
    #pragma unroll
    for (int mi = 0; mi < 2; ++mi) {
        #pragma unroll
        for (int h = 0; h < 2; ++h) {
            int qq = mi * 2 + h;
            int pl = wm * 32 + mi * 16 + h * 8 + r0;
            float xq = sxq[pl];
            float b_ = FLT_MAX, s_ = FLT_MAX; int i_ = 0;
            #pragma unroll
            for (int ni = 0; ni < 8; ++ni) {
                #pragma unroll
                for (int u = 0; u < 2; ++u) {
                    int n = wn * 64 + ni * 8 + c0 + u;
                    float d2 = (xq - 2.0f * acc[mi][ni][h * 2 + u]) + scs[n];
                    if (d2 < b_) { s_ = b_; b_ = d2; i_ = n; }
                    else if (d2 < s_) s_ = d2;
                }
            }
            bd[qq] = b_; sd[qq] = s_; bi[qq] = i_;
        }
    }
    #pragma unroll
    for (int off = 1; off <= 2; off <<= 1) {
        #pragma unroll
        for (int qq = 0; qq < 4; ++qq) {
            float obd = __shfl_xor_sync(0xFFFFFFFFu, bd[qq], off);
            int   obi = __shfl_xor_sync(0xFFFFFFFFu, bi[qq], off);
            float osd = __shfl_xor_sync(0xFFFFFFFFu, sd[qq], off);
            bool take = (obd < bd[qq]) || (obd == bd[qq] && obi < bi[qq]);
            float loser = take ? bd[qq] : obd;
            sd[qq] = fminf(fminf(sd[qq], osd), loser);
            if (take) { bd[qq] = obd; bi[qq] = obi; }
        }
    }
    if ((lane & 3) == 0) {
        #pragma unroll
        for (int qq = 0; qq < 4; ++qq) {
            int pl = wm * 32 + (qq >> 1) * 16 + (qq & 1) * 8 + r0;
            redD[pl * 2 + wn] = bd[qq];
            redI[pl * 2 + wn] = bi[qq];
            redS[pl * 2 + wn] = sd[qq];
        }
    }
    __syncthreads();

    if (tid < 128) {
        int p = p0 + tid;
        if (p < m) {
            float b_ = redD[tid * 2], s_ = redS[tid * 2];
            int i_ = redI[tid * 2];
            float od = redD[tid * 2 + 1], os = redS[tid * 2 + 1];
            int oi = redI[tid * 2 + 1];
            bool take = (od < b_) || (od == b_ && oi < i_);
            float loser = take ? b_ : od;
            s_ = fminf(fminf(s_, os), loser);
            if (take) { b_ = od; i_ = oi; }
            g_clusters[p] = i_;
            s_cid[tid] = i_;
            if (s_ - b_ < TAU) {
                int w = atomicAdd(&s_nf, 1);
                s_fl[w] = tid;
            }
        } else {
            s_cid[tid] = 0;
        }
    }
    __syncthreads();

    // Zero the sums overlay (Cs region is dead now).
    for (int i = tid; i < KCLUST * NDIM; i += 256) sums[i] = 0.0f;

    // Fused near-tie refinement: fp64 dot, reference fp32 op order, first-wins.
    int nf = s_nf;
    for (int f = 0; f < nf; ++f) {
        int pl = s_fl[f];
        int p = p0 + pl;
        if (tid < 128) {
            const float* xr = X + (size_t)p * NDIM;
            const float* cr = g_cent + tid * NDIM;
            double ac[8] = {0, 0, 0, 0, 0, 0, 0, 0};
            #pragma unroll
            for (int k = 0; k < 16; ++k)
                #pragma unroll
                for (int j = 0; j < 8; ++j)
                    ac[j] += (double)xr[k * 8 + j] * (double)cr[k * 8 + j];
            double dot = ((ac[0] + ac[1]) + (ac[2] + ac[3])) +
                         ((ac[4] + ac[5]) + (ac[6] + ac[7]));
            float dotf = (float)dot;
            float t = sxq[pl] - 2.0f * dotf;
            float d2 = t + scs[tid];
            sD[tid] = d2; sI[tid] = tid;
        }
        __syncthreads();
        #pragma unroll
        for (int o = 64; o; o >>= 1) {
            if (tid < o) {
                float d = sD[tid + o]; int cc = sI[tid + o];
                if (d < sD[tid] || (d == sD[tid] && cc < sI[tid])) {
                    sD[tid] = d; sI[tid] = cc;
                }
            }
            __syncthreads();
        }
        if (tid == 0) { g_clusters[p] = sI[0]; s_cid[pl] = sI[0]; }
        __syncthreads();
    }
    __syncthreads();

    // Fused segment accumulation: exact X reads, deterministic point order.
    int npts = m - p0; if (npts > 128) npts = 128;
    if (tid < 128) {
        int i = 0;
        for (; i + 7 < npts; i += 8) {
            int cc8[8]; float xv8[8];
            #pragma unroll
            for (int j = 0; j < 8; ++j) cc8[j] = s_cid[i + j];
            #pragma unroll
            for (int j = 0; j < 8; ++j)
                xv8[j] = X[(size_t)(p0 + i + j) * NDIM + tid];
            #pragma unroll
            for (int j = 0; j < 8; ++j)
                sums[cc8[j] * NDIM + tid] += xv8[j];
        }
        for (; i < npts; ++i)
            sums[s_cid[i] * NDIM + tid] += X[(size_t)(p0 + i) * NDIM + tid];
    }
    __syncthreads();

    float* part = g_part[blockIdx.x];
    for (int k = tid; k < KCLUST * NDIM; k += 256) part[k] = sums[k];
    if (tid < 128) {
        int cnt = 0;
        for (int i = 0; i < npts; ++i) cnt += (s_cid[i] == tid);
        if (cnt) atomicAdd(&g_counts[tid], cnt);
    }
}

// ---------------------------------------------------------------------------
// Update A: merge nb fp32 partials in fp64 (8 slices x 128 dims per block),
// fp32 divide like reference, convergence votes, reset counters.
// ---------------------------------------------------------------------------
__global__ void __launch_bounds__(1024)
update_a_kernel(int iter, int nb) {
    if (*(volatile int*)&g_done) return;
    int k = blockIdx.x;
    int j = threadIdx.x & 127;
    int s = threadIdx.x >> 7;     // slice 0..7
    int idx = k * NDIM + j;

    int chunk = (nb + 7) >> 3;
    int b0 = s * chunk;
    int b1 = b0 + chunk; if (b1 > nb) b1 = nb;

    double a4[4] = {0, 0, 0, 0};
    int b = b0;
    for (; b + 3 < b1; b += 4) {
        #pragma unroll
        for (int u = 0; u < 4; ++u) a4[u] += (double)g_part[b + u][idx];
    }
    for (; b < b1; ++b) a4[0] += (double)g_part[b][idx];
    double accv = (a4[0] + a4[1]) + (a4[2] + a4[3]);

    __shared__ double sdm[1024];
    sdm[threadIdx.x] = accv;
    __syncthreads();
    #pragma unroll
    for (int off = 4; off; off >>= 1) {
        if (s < off) sdm[threadIdx.x] += sdm[threadIdx.x + off * 128];
        __syncthreads();
    }

    __shared__ float rb[128];
    if (threadIdx.x < 128) {
        float sf = (float)sdm[j];
        int cnt = g_counts[k];
        float old = g_cent[idx];
        float newc = (cnt > 0) ? (sf / fmaxf((float)cnt, 1.0f)) : old;
        g_cent_new[idx] = newc;
        float d = newc - old;
        rb[j] = d * d;
    }
    __syncthreads();
    #pragma unroll
    for (int o = 64; o; o >>= 1) {
        if (threadIdx.x < o) rb[threadIdx.x] += rb[threadIdx.x + o];
        __syncthreads();
    }
    if (threadIdx.x == 0) {
        if (rb[0] < 1e-8f) atomicAdd(&g_conv[iter], 1);
        g_counts[k] = 0;
    }
}

// ---------------------------------------------------------------------------
__global__ void __launch_bounds__(128)
update_b_kernel(int iter) {
    if (*(volatile int*)&g_done) return;
    int k = blockIdx.x, j = threadIdx.x;
    int cv = g_conv[iter];
    if (cv == KCLUST) {
        if (k == 0 && j == 0) g_done = 1;
        return;
    }
    int idx = k * NDIM + j;
    float v = g_cent_new[idx];
    g_cent[idx] = v;
    __nv_bfloat16 hi = __float2bfloat16(v);
    g_chi[idx] = hi;
    g_clo[idx] = __float2bfloat16(v - __bfloat162float(hi));

    __shared__ double rb[128];
    rb[j] = (double)v * (double)v;
    __syncthreads();
    #pragma unroll
    for (int o = 64; o; o >>= 1) {
        if (j < o) rb[j] += rb[j + o];
        __syncthreads();
    }
    if (j == 0) g_csqf[k] = (float)rb[0];
}

// ---------------------------------------------------------------------------
__global__ void finalize_kernel(float* __restrict__ out, int m, int out_size) {
    int idx = blockIdx.x * 256 + threadIdx.x;
    const int nc = KCLUST * NDIM;
    if (out_size >= nc + m) {
        if (idx < nc) out[idx] = g_cent[idx];
        else if (idx < nc + m) out[idx] = (float)g_clusters[idx - nc];
    } else if (out_size == m) {
        if (idx < m) out[idx] = (float)g_clusters[idx];
    } else {
        if (idx < out_size && idx < nc) out[idx] = g_cent[idx];
    }
}

// ---------------------------------------------------------------------------
extern "C" void kernel_launch(void* const* d_in, const int* in_sizes, int n_in,
                              void* d_out, int out_size) {
    const float* X  = (const float*)d_in[0];
    const float* C0 = (const float*)d_in[1];
    int m = in_sizes[0] / NDIM;
    if (m > MAX_M) m = MAX_M;

    cudaFuncSetAttribute(assign_tc_kernel,
                         cudaFuncAttributeMaxDynamicSharedMemorySize,
                         ASSIGN_TC_SMEM);

    init_kernel<<<129, 128>>>(C0);
    xprep_kernel<<<(MAX_M + 7) / 8, 256>>>(X, m);

    int ablocks = (m + 127) / 128;
    for (int it = 0; it < MAXIT; ++it) {
        assign_tc_kernel<<<ablocks, 256, ASSIGN_TC_SMEM>>>(X, m);
        update_a_kernel<<<128, 1024>>>(it, ablocks);
        update_b_kernel<<<128, 128>>>(it);
    }

    int fb = (out_size + 255) / 256;
    if (fb < 1) fb = 1;
    finalize_kernel<<<fb, 256>>>((float*)d_out, m, out_size);
}

// round 11
// speedup vs baseline: 1.3689x; 1.3689x over previous
#include <cuda_runtime.h>
#include <cuda_bf16.h>
#include <cfloat>
#include <cstdint>

// ---------------------------------------------------------------------------
// K-means: X [m,128] fp32, centroids_init [128,128] fp32, K=128, 15 iters,
// tol=1e-4. Round-8 pipeline (best known): bf16-split tensor-core assign w/
// fused fp64 near-tie refinement; accum reads exact X into 148 fp32 block
// partials; NEW slice-parallel fp64 merge in update_a (1024 threads).
// ---------------------------------------------------------------------------

#define KCLUST 128
#define NDIM   128
#define MAXIT  15
#define MAX_M  100352
#define NBLK_ACC 148
#define TAU 4e-3f
#define APITCH 72   // bf16 pitch for 64-col smem tiles (conflict-free ldmatrix)

__device__ float  g_cent[KCLUST * NDIM];
__device__ float  g_cent_new[KCLUST * NDIM];
__device__ float  g_csqf[KCLUST];
__device__ float  g_part[NBLK_ACC][KCLUST * NDIM];
__device__ int    g_counts[KCLUST];
__device__ int    g_clusters[MAX_M];
__device__ float  g_xsq[MAX_M];
__device__ int    g_conv[MAXIT + 1];
__device__ int    g_done;

__device__ __nv_bfloat16 g_xhi[MAX_M * NDIM];
__device__ __nv_bfloat16 g_xlo[MAX_M * NDIM];
__device__ __nv_bfloat16 g_chi[KCLUST * NDIM];
__device__ __nv_bfloat16 g_clo[KCLUST * NDIM];

// ---------------------------------------------------------------------------
__global__ void init_kernel(const float* __restrict__ c0) {
    int b = blockIdx.x, t = threadIdx.x;
    if (b < 128) {
        int idx = b * 128 + t;
        float v = c0[idx];
        g_cent[idx] = v;
        __nv_bfloat16 hi = __float2bfloat16(v);
        g_chi[idx] = hi;
        g_clo[idx] = __float2bfloat16(v - __bfloat162float(hi));
        __shared__ double rb[128];
        rb[t] = (double)v * (double)v;
        __syncthreads();
        #pragma unroll
        for (int o = 64; o; o >>= 1) {
            if (t < o) rb[t] += rb[t + o];
            __syncthreads();
        }
        if (t == 0) g_csqf[b] = (float)rb[0];
    } else {
        if (t < KCLUST) g_counts[t] = 0;
        if (t < MAXIT + 1) g_conv[t] = 0;
        if (t == 0) g_done = 0;
    }
}

// ---------------------------------------------------------------------------
// One-time: fused x_sq (fp64->fp32) + bf16 split of X (+ zero padded rows).
// ---------------------------------------------------------------------------
__global__ void __launch_bounds__(256)
xprep_kernel(const float* __restrict__ X, int m) {
    int row = blockIdx.x * 8 + (threadIdx.x >> 5);
    int lane = threadIdx.x & 31;
    if (row >= MAX_M) return;
    __nv_bfloat162* hip = (__nv_bfloat162*)(g_xhi + (size_t)row * NDIM + lane * 4);
    __nv_bfloat162* lop = (__nv_bfloat162*)(g_xlo + (size_t)row * NDIM + lane * 4);
    if (row < m) {
        float4 v = *reinterpret_cast<const float4*>(&X[(size_t)row * NDIM + lane * 4]);
        float f[4] = {v.x, v.y, v.z, v.w};
        __nv_bfloat16 h[4], l[4];
        #pragma unroll
        for (int j = 0; j < 4; ++j) {
            h[j] = __float2bfloat16(f[j]);
            l[j] = __float2bfloat16(f[j] - __bfloat162float(h[j]));
        }
        hip[0] = __nv_bfloat162(h[0], h[1]);
        hip[1] = __nv_bfloat162(h[2], h[3]);
        lop[0] = __nv_bfloat162(l[0], l[1]);
        lop[1] = __nv_bfloat162(l[2], l[3]);
        double s = (double)v.x * v.x + (double)v.y * v.y +
                   (double)v.z * v.z + (double)v.w * v.w;
        #pragma unroll
        for (int o = 16; o; o >>= 1) s += __shfl_xor_sync(0xFFFFFFFFu, s, o);
        if (lane == 0) g_xsq[row] = (float)s;
    } else {
        __nv_bfloat162 z(__float2bfloat16(0.0f), __float2bfloat16(0.0f));
        hip[0] = z; hip[1] = z; lop[0] = z; lop[1] = z;
    }
}

// ---------------------------------------------------------------------------
// Assignment: bf16-split tensor-core GEMM + argmin + fused in-block fp64
// refinement of near-ties (replays reference fp32 op order, first-index-wins).
// ---------------------------------------------------------------------------
#define LDSM_X4(r0, r1, r2, r3, addr) \
    asm volatile("ldmatrix.sync.aligned.m8n8.x4.shared.b16 {%0,%1,%2,%3}, [%4];" \
        : "=r"(r0), "=r"(r1), "=r"(r2), "=r"(r3) : "r"(addr))

#define MMA16816(d, a, b0, b1) \
    asm volatile("mma.sync.aligned.m16n8k16.row.col.f32.bf16.bf16.f32 " \
        "{%0,%1,%2,%3},{%4,%5,%6,%7},{%8,%9},{%0,%1,%2,%3};" \
        : "+f"(d[0]), "+f"(d[1]), "+f"(d[2]), "+f"(d[3]) \
        : "r"(a[0]), "r"(a[1]), "r"(a[2]), "r"(a[3]), "r"(b0), "r"(b1))

#define TILE_B (128 * APITCH)
#define TILE_BYTES (TILE_B * 2)
#define ASSIGN_TC_SMEM (6 * TILE_BYTES + 1024)

__global__ void __launch_bounds__(256, 2)
assign_tc_kernel(const float* __restrict__ X, int m) {
    if (*(volatile int*)&g_done) return;

    extern __shared__ char sm8[];
    __nv_bfloat16* Cs = (__nv_bfloat16*)sm8;         // 4 centroid chunks
    __nv_bfloat16* As = Cs + 4 * TILE_B;             // 2 A buffers
    float* scs = (float*)(As + 2 * TILE_B);
    float* sxq = scs + 128;
    float* redD = (float*)sm8;                       // overlays Cs post-GEMM
    int*   redI = (int*)(sm8 + 2048);
    float* redS = (float*)(sm8 + 4096);

    __shared__ int   s_nf;
    __shared__ int   s_fl[128];
    __shared__ float sD[128];
    __shared__ int   sI[128];

    const int tid = threadIdx.x;
    const int lane = tid & 31;
    const int wid = tid >> 5;
    const int wm = wid & 3;
    const int wn = wid >> 2;
    const int p0 = blockIdx.x * 128;

    if (tid == 0) s_nf = 0;
    if (tid < 128) {
        scs[tid] = g_csqf[tid];
        int p = p0 + tid;
        sxq[tid] = (p < m) ? g_xsq[p] : 0.0f;
    }

    #pragma unroll
    for (int ch = 0; ch < 4; ++ch) {
        const __nv_bfloat16* Bp = (ch < 2) ? g_chi : g_clo;
        int kc = (ch & 1) * 64;
        #pragma unroll
        for (int i = 0; i < 4; ++i) {
            int lin = tid + i * 256;
            int row = lin >> 3, c8 = lin & 7;
            uint4 vb = *(const uint4*)(Bp + row * 128 + kc + c8 * 8);
            *(uint4*)(Cs + ch * TILE_B + row * APITCH + c8 * 8) = vb;
        }
    }

    uint4 nxt[4];
    {
        #pragma unroll
        for (int i = 0; i < 4; ++i) {
            int lin = tid + i * 256;
            int row = lin >> 3, c8 = lin & 7;
            nxt[i] = *(const uint4*)(g_xhi + (size_t)(p0 + row) * 128 + c8 * 8);
        }
        #pragma unroll
        for (int i = 0; i < 4; ++i) {
            int lin = tid + i * 256;
            int row = lin >> 3, c8 = lin & 7;
            *(uint4*)(As + row * APITCH + c8 * 8) = nxt[i];
        }
    }
    __syncthreads();

    const int q = lane >> 3;
    const int r = lane & 7;
    uint32_t asBase = (uint32_t)__cvta_generic_to_shared(As);
    uint32_t csBase = (uint32_t)__cvta_generic_to_shared(Cs);
    uint32_t aoff[2];
    #pragma unroll
    for (int mi = 0; mi < 2; ++mi)
        aoff[mi] = asBase +
            (uint32_t)(((wm * 32 + mi * 16 + (q & 1) * 8 + r) * APITCH + (q >> 1) * 8) * 2);
    uint32_t boff[4];
    #pragma unroll
    for (int nip = 0; nip < 4; ++nip)
        boff[nip] = csBase +
            (uint32_t)(((wn * 64 + nip * 16 + (q >> 1) * 8 + r) * APITCH + (q & 1) * 8) * 2);

    float acc[2][8][4];
    #pragma unroll
    for (int mi = 0; mi < 2; ++mi)
        #pragma unroll
        for (int ni = 0; ni < 8; ++ni)
            #pragma unroll
            for (int u = 0; u < 4; ++u) acc[mi][ni][u] = 0.0f;

    #pragma unroll 1
    for (int s = 0; s < 4; ++s) {
        if (s < 3) {
            const __nv_bfloat16* Ap = (s + 1 < 2) ? g_xhi : g_xlo;
            int kc = ((s + 1) & 1) * 64;
            #pragma unroll
            for (int i = 0; i < 4; ++i) {
                int lin = tid + i * 256;
                int row = lin >> 3, c8 = lin & 7;
                nxt[i] = *(const uint4*)(Ap + (size_t)(p0 + row) * 128 + kc + c8 * 8);
            }
        }

        const uint32_t abuf = (uint32_t)(s & 1) * TILE_BYTES;
        const uint32_t hiB = (uint32_t)(s & 1) * TILE_BYTES;
        const uint32_t loB = (uint32_t)(2 + (s & 1)) * TILE_BYTES;
        const bool doLo = (s < 2);

        #pragma unroll
        for (int ks = 0; ks < 4; ++ks) {
            uint32_t a[2][4];
            #pragma unroll
            for (int mi = 0; mi < 2; ++mi)
                LDSM_X4(a[mi][0], a[mi][1], a[mi][2], a[mi][3],
                        aoff[mi] + abuf + ks * 32);
            uint32_t b[4][4];
            #pragma unroll
            for (int nip = 0; nip < 4; ++nip)
                LDSM_X4(b[nip][0], b[nip][1], b[nip][2], b[nip][3],
                        boff[nip] + hiB + ks * 32);
            #pragma unroll
            for (int mi = 0; mi < 2; ++mi)
                #pragma unroll
                for (int nip = 0; nip < 4; ++nip) {
                    MMA16816(acc[mi][nip * 2 + 0], a[mi], b[nip][0], b[nip][1]);
                    MMA16816(acc[mi][nip * 2 + 1], a[mi], b[nip][2], b[nip][3]);
                }
            if (doLo) {
                #pragma unroll
                for (int nip = 0; nip < 4; ++nip)
                    LDSM_X4(b[nip][0], b[nip][1], b[nip][2], b[nip][3],
                            boff[nip] + loB + ks * 32);
                #pragma unroll
                for (int mi = 0; mi < 2; ++mi)
                    #pragma unroll
                    for (int nip = 0; nip < 4; ++nip) {
                        MMA16816(acc[mi][nip * 2 + 0], a[mi], b[nip][0], b[nip][1]);
                        MMA16816(acc[mi][nip * 2 + 1], a[mi], b[nip][2], b[nip][3]);
                    }
            }
        }

        if (s < 3) {
            #pragma unroll
            for (int i = 0; i < 4; ++i) {
                int lin = tid + i * 256;
                int row = lin >> 3, c8 = lin & 7;
                *(uint4*)(As + ((s + 1) & 1) * TILE_B + row * APITCH + c8 * 8) = nxt[i];
            }
        }
        __syncthreads();
    }

    const int r0 = lane >> 2;
    const int c0 = (lane & 3) * 2;
    float bd[4], sd[4]; int bi[4];
    #pragma unroll
    for (int mi = 0; mi < 2; ++mi) {
        #pragma unroll
        for (int h = 0; h < 2; ++h) {
            int qq = mi * 2 + h;
            int pl = wm * 32 + mi * 16 + h * 8 + r0;
            float xq = sxq[pl];
            float b_ = FLT_MAX, s_ = FLT_MAX; int i_ = 0;
            #pragma unroll
            for (int ni = 0; ni < 8; ++ni) {
                #pragma unroll
                for (int u = 0; u < 2; ++u) {
                    int n = wn * 64 + ni * 8 + c0 + u;
                    float d2 = (xq - 2.0f * acc[mi][ni][h * 2 + u]) + scs[n];
                    if (d2 < b_) { s_ = b_; b_ = d2; i_ = n; }
                    else if (d2 < s_) s_ = d2;
                }
            }
            bd[qq] = b_; sd[qq] = s_; bi[qq] = i_;
        }
    }
    #pragma unroll
    for (int off = 1; off <= 2; off <<= 1) {
        #pragma unroll
        for (int qq = 0; qq < 4; ++qq) {
            float obd = __shfl_xor_sync(0xFFFFFFFFu, bd[qq], off);
            int   obi = __shfl_xor_sync(0xFFFFFFFFu, bi[qq], off);
            float osd = __shfl_xor_sync(0xFFFFFFFFu, sd[qq], off);
            bool take = (obd < bd[qq]) || (obd == bd[qq] && obi < bi[qq]);
            float loser = take ? bd[qq] : obd;
            sd[qq] = fminf(fminf(sd[qq], osd), loser);
            if (take) { bd[qq] = obd; bi[qq] = obi; }
        }
    }
    if ((lane & 3) == 0) {
        #pragma unroll
        for (int qq = 0; qq < 4; ++qq) {
            int pl = wm * 32 + (qq >> 1) * 16 + (qq & 1) * 8 + r0;
            redD[pl * 2 + wn] = bd[qq];
            redI[pl * 2 + wn] = bi[qq];
            redS[pl * 2 + wn] = sd[qq];
        }
    }
    __syncthreads();

    if (tid < 128) {
        int p = p0 + tid;
        if (p < m) {
            float b_ = redD[tid * 2], s_ = redS[tid * 2];
            int i_ = redI[tid * 2];
            float od = redD[tid * 2 + 1], os = redS[tid * 2 + 1];
            int oi = redI[tid * 2 + 1];
            bool take = (od < b_) || (od == b_ && oi < i_);
            float loser = take ? b_ : od;
            s_ = fminf(fminf(s_, os), loser);
            if (take) { b_ = od; i_ = oi; }
            g_clusters[p] = i_;
            if (s_ - b_ < TAU) {
                int w = atomicAdd(&s_nf, 1);
                s_fl[w] = tid;
            }
        }
    }
    __syncthreads();

    int nf = s_nf;
    for (int f = 0; f < nf; ++f) {
        int pl = s_fl[f];
        int p = p0 + pl;
        if (tid < 128) {
            const float* xr = X + (size_t)p * NDIM;
            const float* cr = g_cent + tid * NDIM;
            double ac[8] = {0, 0, 0, 0, 0, 0, 0, 0};
            #pragma unroll
            for (int k = 0; k < 16; ++k)
                #pragma unroll
                for (int j = 0; j < 8; ++j)
                    ac[j] += (double)xr[k * 8 + j] * (double)cr[k * 8 + j];
            double dot = ((ac[0] + ac[1]) + (ac[2] + ac[3])) +
                         ((ac[4] + ac[5]) + (ac[6] + ac[7]));
            float dotf = (float)dot;
            float t = sxq[pl] - 2.0f * dotf;
            float d2 = t + scs[tid];
            sD[tid] = d2; sI[tid] = tid;
        }
        __syncthreads();
        #pragma unroll
        for (int o = 64; o; o >>= 1) {
            if (tid < o) {
                float d = sD[tid + o]; int cc = sI[tid + o];
                if (d < sD[tid] || (d == sD[tid] && cc < sI[tid])) {
                    sD[tid] = d; sI[tid] = cc;
                }
            }
            __syncthreads();
        }
        if (tid == 0) g_clusters[p] = sI[0];
        __syncthreads();
    }
}

// ---------------------------------------------------------------------------
// Segment accumulation: EXACT fp32 X reads, two private smem accumulator
// groups (race-free +=), 16-point batches for MLP, fp32 block partials.
// ---------------------------------------------------------------------------
#define ACCUM_SMEM_BYTES (2 * KCLUST * NDIM * 4 + 2 * KCLUST * 4)

__global__ void __launch_bounds__(256)
accum_kernel(const float* __restrict__ X, int m) {
    if (*(volatile int*)&g_done) return;

    extern __shared__ float sm_f[];                 // 2 x 16384 floats
    int* scnt = (int*)(sm_f + 2 * KCLUST * NDIM);   // 2 x 128 ints

    const int tid = threadIdx.x;
    const int grp = tid >> 7;          // 0 / 1
    const int dim = tid & 127;
    float* ssum = sm_f + grp * (KCLUST * NDIM);
    int* mycnt = scnt + grp * 128;

    for (int i = tid; i < 2 * KCLUST * NDIM; i += 256) sm_f[i] = 0.0f;
    scnt[tid] = 0;
    __syncthreads();

    int chunk = (m + NBLK_ACC - 1) / NBLK_ACC;
    int lo = blockIdx.x * chunk;
    int hi = lo + chunk; if (hi > m) hi = m;

    int i = lo + grp;
    for (; i + 30 < hi; i += 32) {      // 16 points per group, stride 2
        int cc[16]; float xv[16];
        #pragma unroll
        for (int j = 0; j < 16; ++j) cc[j] = g_clusters[i + 2 * j];
        #pragma unroll
        for (int j = 0; j < 16; ++j)
            xv[j] = X[(size_t)(i + 2 * j) * NDIM + dim];
        if (dim == 0) {
            #pragma unroll
            for (int j = 0; j < 16; ++j) mycnt[cc[j]]++;
        }
        #pragma unroll
        for (int j = 0; j < 16; ++j)
            ssum[cc[j] * NDIM + dim] += xv[j];
    }
    for (; i < hi; i += 2) {
        int c = g_clusters[i];
        float x = X[(size_t)i * NDIM + dim];
        if (dim == 0) mycnt[c]++;
        ssum[c * NDIM + dim] += x;
    }
    __syncthreads();

    float* part = g_part[blockIdx.x];
    for (int k = tid; k < KCLUST * NDIM; k += 256)
        part[k] = sm_f[k] + sm_f[KCLUST * NDIM + k];
    if (tid < 128) {
        int c = scnt[tid] + scnt[128 + tid];
        if (c) atomicAdd(&g_counts[tid], c);
    }
}

// ---------------------------------------------------------------------------
// Update A: slice-parallel fp64 merge of 148 fp32 partials (1024 threads:
// 8 slices x 128 dims), fp32 divide like reference, convergence votes.
// ---------------------------------------------------------------------------
__global__ void __launch_bounds__(1024)
update_a_kernel(int iter) {
    if (*(volatile int*)&g_done) return;
    int k = blockIdx.x;
    int j = threadIdx.x & 127;
    int s = threadIdx.x >> 7;     // slice 0..7
    int idx = k * NDIM + j;

    const int chunk = (NBLK_ACC + 7) >> 3;   // 19
    int b0 = s * chunk;
    int b1 = b0 + chunk; if (b1 > NBLK_ACC) b1 = NBLK_ACC;

    double a4[4] = {0, 0, 0, 0};
    int b = b0;
    for (; b + 3 < b1; b += 4) {
        #pragma unroll
        for (int u = 0; u < 4; ++u) a4[u] += (double)g_part[b + u][idx];
    }
    for (; b < b1; ++b) a4[0] += (double)g_part[b][idx];
    double accv = (a4[0] + a4[1]) + (a4[2] + a4[3]);

    __shared__ double sdm[1024];
    sdm[threadIdx.x] = accv;
    __syncthreads();
    #pragma unroll
    for (int off = 4; off; off >>= 1) {
        if (s < off) sdm[threadIdx.x] += sdm[threadIdx.x + off * 128];
        __syncthreads();
    }

    __shared__ float rb[128];
    if (threadIdx.x < 128) {
        float sf = (float)sdm[j];
        int cnt = g_counts[k];
        float old = g_cent[idx];
        float newc = (cnt > 0) ? (sf / fmaxf((float)cnt, 1.0f)) : old;
        g_cent_new[idx] = newc;
        float d = newc - old;
        rb[j] = d * d;
    }
    __syncthreads();
    #pragma unroll
    for (int o = 64; o; o >>= 1) {
        if (threadIdx.x < o) rb[threadIdx.x] += rb[threadIdx.x + o];
        __syncthreads();
    }
    if (threadIdx.x == 0) {
        if (rb[0] < 1e-8f) atomicAdd(&g_conv[iter], 1);
        g_counts[k] = 0;
    }
}

// ---------------------------------------------------------------------------
__global__ void __launch_bounds__(128)
update_b_kernel(int iter) {
    if (*(volatile int*)&g_done) return;
    int k = blockIdx.x, j = threadIdx.x;
    int cv = g_conv[iter];
    if (cv == KCLUST) {
        if (k == 0 && j == 0) g_done = 1;
        return;
    }
    int idx = k * NDIM + j;
    float v = g_cent_new[idx];
    g_cent[idx] = v;
    __nv_bfloat16 hi = __float2bfloat16(v);
    g_chi[idx] = hi;
    g_clo[idx] = __float2bfloat16(v - __bfloat162float(hi));

    __shared__ double rb[128];
    rb[j] = (double)v * (double)v;
    __syncthreads();
    #pragma unroll
    for (int o = 64; o; o >>= 1) {
        if (j < o) rb[j] += rb[j + o];
        __syncthreads();
    }
    if (j == 0) g_csqf[k] = (float)rb[0];
}

// ---------------------------------------------------------------------------
__global__ void finalize_kernel(float* __restrict__ out, int m, int out_size) {
    int idx = blockIdx.x * 256 + threadIdx.x;
    const int nc = KCLUST * NDIM;
    if (out_size >= nc + m) {
        if (idx < nc) out[idx] = g_cent[idx];
        else if (idx < nc + m) out[idx] = (float)g_clusters[idx - nc];
    } else if (out_size == m) {
        if (idx < m) out[idx] = (float)g_clusters[idx];
    } else {
        if (idx < out_size && idx < nc) out[idx] = g_cent[idx];
    }
}

// ---------------------------------------------------------------------------
extern "C" void kernel_launch(void* const* d_in, const int* in_sizes, int n_in,
                              void* d_out, int out_size) {
    const float* X  = (const float*)d_in[0];
    const float* C0 = (const float*)d_in[1];
    int m = in_sizes[0] / NDIM;
    if (m > MAX_M) m = MAX_M;

    cudaFuncSetAttribute(assign_tc_kernel,
                         cudaFuncAttributeMaxDynamicSharedMemorySize,
                         ASSIGN_TC_SMEM);
    cudaFuncSetAttribute(accum_kernel,
                         cudaFuncAttributeMaxDynamicSharedMemorySize,
                         ACCUM_SMEM_BYTES);

    init_kernel<<<129, 128>>>(C0);
    xprep_kernel<<<(MAX_M + 7) / 8, 256>>>(X, m);

    int ablocks = (m + 127) / 128;
    for (int it = 0; it < MAXIT; ++it) {
        assign_tc_kernel<<<ablocks, 256, ASSIGN_TC_SMEM>>>(X, m);
        accum_kernel<<<NBLK_ACC, 256, ACCUM_SMEM_BYTES>>>(X, m);
        update_a_kernel<<<128, 1024>>>(it);
        update_b_kernel<<<128, 128>>>(it);
    }

    int fb = (out_size + 255) / 256;
    if (fb < 1) fb = 1;
    finalize_kernel<<<fb, 256>>>((float*)d_out, m, out_size);
}

// round 12
// speedup vs baseline: 1.4461x; 1.0563x over previous
#include <cuda_runtime.h>
#include <cuda_bf16.h>
#include <cfloat>
#include <cstdint>

// ---------------------------------------------------------------------------
// K-means: X [m,128] fp32, centroids_init [128,128] fp32, K=128, 15 iters,
// tol=1e-4. Round-11 pipeline: bf16-split tensor-core assign w/ fused fp64
// near-tie refinement; accum reads exact X (NOW 3 accumulator groups, 384
// threads) into 148 fp32 block partials; slice-parallel fp64 merge.
// ---------------------------------------------------------------------------

#define KCLUST 128
#define NDIM   128
#define MAXIT  15
#define MAX_M  100352
#define NBLK_ACC 148
#define TAU 4e-3f
#define APITCH 72   // bf16 pitch for 64-col smem tiles (conflict-free ldmatrix)

__device__ float  g_cent[KCLUST * NDIM];
__device__ float  g_cent_new[KCLUST * NDIM];
__device__ float  g_csqf[KCLUST];
__device__ float  g_part[NBLK_ACC][KCLUST * NDIM];
__device__ int    g_counts[KCLUST];
__device__ int    g_clusters[MAX_M];
__device__ float  g_xsq[MAX_M];
__device__ int    g_conv[MAXIT + 1];
__device__ int    g_done;

__device__ __nv_bfloat16 g_xhi[MAX_M * NDIM];
__device__ __nv_bfloat16 g_xlo[MAX_M * NDIM];
__device__ __nv_bfloat16 g_chi[KCLUST * NDIM];
__device__ __nv_bfloat16 g_clo[KCLUST * NDIM];

// ---------------------------------------------------------------------------
__global__ void init_kernel(const float* __restrict__ c0) {
    int b = blockIdx.x, t = threadIdx.x;
    if (b < 128) {
        int idx = b * 128 + t;
        float v = c0[idx];
        g_cent[idx] = v;
        __nv_bfloat16 hi = __float2bfloat16(v);
        g_chi[idx] = hi;
        g_clo[idx] = __float2bfloat16(v - __bfloat162float(hi));
        __shared__ double rb[128];
        rb[t] = (double)v * (double)v;
        __syncthreads();
        #pragma unroll
        for (int o = 64; o; o >>= 1) {
            if (t < o) rb[t] += rb[t + o];
            __syncthreads();
        }
        if (t == 0) g_csqf[b] = (float)rb[0];
    } else {
        if (t < KCLUST) g_counts[t] = 0;
        if (t < MAXIT + 1) g_conv[t] = 0;
        if (t == 0) g_done = 0;
    }
}

// ---------------------------------------------------------------------------
// One-time: fused x_sq (fp64->fp32) + bf16 split of X (+ zero padded rows).
// ---------------------------------------------------------------------------
__global__ void __launch_bounds__(256)
xprep_kernel(const float* __restrict__ X, int m) {
    int row = blockIdx.x * 8 + (threadIdx.x >> 5);
    int lane = threadIdx.x & 31;
    if (row >= MAX_M) return;
    __nv_bfloat162* hip = (__nv_bfloat162*)(g_xhi + (size_t)row * NDIM + lane * 4);
    __nv_bfloat162* lop = (__nv_bfloat162*)(g_xlo + (size_t)row * NDIM + lane * 4);
    if (row < m) {
        float4 v = *reinterpret_cast<const float4*>(&X[(size_t)row * NDIM + lane * 4]);
        float f[4] = {v.x, v.y, v.z, v.w};
        __nv_bfloat16 h[4], l[4];
        #pragma unroll
        for (int j = 0; j < 4; ++j) {
            h[j] = __float2bfloat16(f[j]);
            l[j] = __float2bfloat16(f[j] - __bfloat162float(h[j]));
        }
        hip[0] = __nv_bfloat162(h[0], h[1]);
        hip[1] = __nv_bfloat162(h[2], h[3]);
        lop[0] = __nv_bfloat162(l[0], l[1]);
        lop[1] = __nv_bfloat162(l[2], l[3]);
        double s = (double)v.x * v.x + (double)v.y * v.y +
                   (double)v.z * v.z + (double)v.w * v.w;
        #pragma unroll
        for (int o = 16; o; o >>= 1) s += __shfl_xor_sync(0xFFFFFFFFu, s, o);
        if (lane == 0) g_xsq[row] = (float)s;
    } else {
        __nv_bfloat162 z(__float2bfloat16(0.0f), __float2bfloat16(0.0f));
        hip[0] = z; hip[1] = z; lop[0] = z; lop[1] = z;
    }
}

// ---------------------------------------------------------------------------
// Assignment: bf16-split tensor-core GEMM + argmin + fused in-block fp64
// refinement of near-ties (replays reference fp32 op order, first-index-wins).
// ---------------------------------------------------------------------------
#define LDSM_X4(r0, r1, r2, r3, addr) \
    asm volatile("ldmatrix.sync.aligned.m8n8.x4.shared.b16 {%0,%1,%2,%3}, [%4];" \
        : "=r"(r0), "=r"(r1), "=r"(r2), "=r"(r3) : "r"(addr))

#define MMA16816(d, a, b0, b1) \
    asm volatile("mma.sync.aligned.m16n8k16.row.col.f32.bf16.bf16.f32 " \
        "{%0,%1,%2,%3},{%4,%5,%6,%7},{%8,%9},{%0,%1,%2,%3};" \
        : "+f"(d[0]), "+f"(d[1]), "+f"(d[2]), "+f"(d[3]) \
        : "r"(a[0]), "r"(a[1]), "r"(a[2]), "r"(a[3]), "r"(b0), "r"(b1))

#define TILE_B (128 * APITCH)
#define TILE_BYTES (TILE_B * 2)
#define ASSIGN_TC_SMEM (6 * TILE_BYTES + 1024)

__global__ void __launch_bounds__(256, 2)
assign_tc_kernel(const float* __restrict__ X, int m) {
    if (*(volatile int*)&g_done) return;

    extern __shared__ char sm8[];
    __nv_bfloat16* Cs = (__nv_bfloat16*)sm8;         // 4 centroid chunks
    __nv_bfloat16* As = Cs + 4 * TILE_B;             // 2 A buffers
    float* scs = (float*)(As + 2 * TILE_B);
    float* sxq = scs + 128;
    float* redD = (float*)sm8;                       // overlays Cs post-GEMM
    int*   redI = (int*)(sm8 + 2048);
    float* redS = (float*)(sm8 + 4096);

    __shared__ int   s_nf;
    __shared__ int   s_fl[128];
    __shared__ float sD[128];
    __shared__ int   sI[128];

    const int tid = threadIdx.x;
    const int lane = tid & 31;
    const int wid = tid >> 5;
    const int wm = wid & 3;
    const int wn = wid >> 2;
    const int p0 = blockIdx.x * 128;

    if (tid == 0) s_nf = 0;
    if (tid < 128) {
        scs[tid] = g_csqf[tid];
        int p = p0 + tid;
        sxq[tid] = (p < m) ? g_xsq[p] : 0.0f;
    }

    #pragma unroll
    for (int ch = 0; ch < 4; ++ch) {
        const __nv_bfloat16* Bp = (ch < 2) ? g_chi : g_clo;
        int kc = (ch & 1) * 64;
        #pragma unroll
        for (int i = 0; i < 4; ++i) {
            int lin = tid + i * 256;
            int row = lin >> 3, c8 = lin & 7;
            uint4 vb = *(const uint4*)(Bp + row * 128 + kc + c8 * 8);
            *(uint4*)(Cs + ch * TILE_B + row * APITCH + c8 * 8) = vb;
        }
    }

    uint4 nxt[4];
    {
        #pragma unroll
        for (int i = 0; i < 4; ++i) {
            int lin = tid + i * 256;
            int row = lin >> 3, c8 = lin & 7;
            nxt[i] = *(const uint4*)(g_xhi + (size_t)(p0 + row) * 128 + c8 * 8);
        }
        #pragma unroll
        for (int i = 0; i < 4; ++i) {
            int lin = tid + i * 256;
            int row = lin >> 3, c8 = lin & 7;
            *(uint4*)(As + row * APITCH + c8 * 8) = nxt[i];
        }
    }
    __syncthreads();

    const int q = lane >> 3;
    const int r = lane & 7;
    uint32_t asBase = (uint32_t)__cvta_generic_to_shared(As);
    uint32_t csBase = (uint32_t)__cvta_generic_to_shared(Cs);
    uint32_t aoff[2];
    #pragma unroll
    for (int mi = 0; mi < 2; ++mi)
        aoff[mi] = asBase +
            (uint32_t)(((wm * 32 + mi * 16 + (q & 1) * 8 + r) * APITCH + (q >> 1) * 8) * 2);
    uint32_t boff[4];
    #pragma unroll
    for (int nip = 0; nip < 4; ++nip)
        boff[nip] = csBase +
            (uint32_t)(((wn * 64 + nip * 16 + (q >> 1) * 8 + r) * APITCH + (q & 1) * 8) * 2);

    float acc[2][8][4];
    #pragma unroll
    for (int mi = 0; mi < 2; ++mi)
        #pragma unroll
        for (int ni = 0; ni < 8; ++ni)
            #pragma unroll
            for (int u = 0; u < 4; ++u) acc[mi][ni][u] = 0.0f;

    #pragma unroll 1
    for (int s = 0; s < 4; ++s) {
        if (s < 3) {
            const __nv_bfloat16* Ap = (s + 1 < 2) ? g_xhi : g_xlo;
            int kc = ((s + 1) & 1) * 64;
            #pragma unroll
            for (int i = 0; i < 4; ++i) {
                int lin = tid + i * 256;
                int row = lin >> 3, c8 = lin & 7;
                nxt[i] = *(const uint4*)(Ap + (size_t)(p0 + row) * 128 + kc + c8 * 8);
            }
        }

        const uint32_t abuf = (uint32_t)(s & 1) * TILE_BYTES;
        const uint32_t hiB = (uint32_t)(s & 1) * TILE_BYTES;
        const uint32_t loB = (uint32_t)(2 + (s & 1)) * TILE_BYTES;
        const bool doLo = (s < 2);

        #pragma unroll
        for (int ks = 0; ks < 4; ++ks) {
            uint32_t a[2][4];
            #pragma unroll
            for (int mi = 0; mi < 2; ++mi)
                LDSM_X4(a[mi][0], a[mi][1], a[mi][2], a[mi][3],
                        aoff[mi] + abuf + ks * 32);
            uint32_t b[4][4];
            #pragma unroll
            for (int nip = 0; nip < 4; ++nip)
                LDSM_X4(b[nip][0], b[nip][1], b[nip][2], b[nip][3],
                        boff[nip] + hiB + ks * 32);
            #pragma unroll
            for (int mi = 0; mi < 2; ++mi)
                #pragma unroll
                for (int nip = 0; nip < 4; ++nip) {
                    MMA16816(acc[mi][nip * 2 + 0], a[mi], b[nip][0], b[nip][1]);
                    MMA16816(acc[mi][nip * 2 + 1], a[mi], b[nip][2], b[nip][3]);
                }
            if (doLo) {
                #pragma unroll
                for (int nip = 0; nip < 4; ++nip)
                    LDSM_X4(b[nip][0], b[nip][1], b[nip][2], b[nip][3],
                            boff[nip] + loB + ks * 32);
                #pragma unroll
                for (int mi = 0; mi < 2; ++mi)
                    #pragma unroll
                    for (int nip = 0; nip < 4; ++nip) {
                        MMA16816(acc[mi][nip * 2 + 0], a[mi], b[nip][0], b[nip][1]);
                        MMA16816(acc[mi][nip * 2 + 1], a[mi], b[nip][2], b[nip][3]);
                    }
            }
        }

        if (s < 3) {
            #pragma unroll
            for (int i = 0; i < 4; ++i) {
                int lin = tid + i * 256;
                int row = lin >> 3, c8 = lin & 7;
                *(uint4*)(As + ((s + 1) & 1) * TILE_B + row * APITCH + c8 * 8) = nxt[i];
            }
        }
        __syncthreads();
    }

    const int r0 = lane >> 2;
    const int c0 = (lane & 3) * 2;
    float bd[4], sd[4]; int bi[4];
    #pragma unroll
    for (int mi = 0; mi < 2; ++mi) {
        #pragma unroll
        for (int h = 0; h < 2; ++h) {
            int qq = mi * 2 + h;
            int pl = wm * 32 + mi * 16 + h * 8 + r0;
            float xq = sxq[pl];
            float b_ = FLT_MAX, s_ = FLT_MAX; int i_ = 0;
            #pragma unroll
            for (int ni = 0; ni < 8; ++ni) {
                #pragma unroll
                for (int u = 0; u < 2; ++u) {
                    int n = wn * 64 + ni * 8 + c0 + u;
                    float d2 = (xq - 2.0f * acc[mi][ni][h * 2 + u]) + scs[n];
                    if (d2 < b_) { s_ = b_; b_ = d2; i_ = n; }
                    else if (d2 < s_) s_ = d2;
                }
            }
            bd[qq] = b_; sd[qq] = s_; bi[qq] = i_;
        }
    }
    #pragma unroll
    for (int off = 1; off <= 2; off <<= 1) {
        #pragma unroll
        for (int qq = 0; qq < 4; ++qq) {
            float obd = __shfl_xor_sync(0xFFFFFFFFu, bd[qq], off);
            int   obi = __shfl_xor_sync(0xFFFFFFFFu, bi[qq], off);
            float osd = __shfl_xor_sync(0xFFFFFFFFu, sd[qq], off);
            bool take = (obd < bd[qq]) || (obd == bd[qq] && obi < bi[qq]);
            float loser = take ? bd[qq] : obd;
            sd[qq] = fminf(fminf(sd[qq], osd), loser);
            if (take) { bd[qq] = obd; bi[qq] = obi; }
        }
    }
    if ((lane & 3) == 0) {
        #pragma unroll
        for (int qq = 0; qq < 4; ++qq) {
            int pl = wm * 32 + (qq >> 1) * 16 + (qq & 1) * 8 + r0;
            redD[pl * 2 + wn] = bd[qq];
            redI[pl * 2 + wn] = bi[qq];
            redS[pl * 2 + wn] = sd[qq];
        }
    }
    __syncthreads();

    if (tid < 128) {
        int p = p0 + tid;
        if (p < m) {
            float b_ = redD[tid * 2], s_ = redS[tid * 2];
            int i_ = redI[tid * 2];
            float od = redD[tid * 2 + 1], os = redS[tid * 2 + 1];
            int oi = redI[tid * 2 + 1];
            bool take = (od < b_) || (od == b_ && oi < i_);
            float loser = take ? b_ : od;
            s_ = fminf(fminf(s_, os), loser);
            if (take) { b_ = od; i_ = oi; }
            g_clusters[p] = i_;
            if (s_ - b_ < TAU) {
                int w = atomicAdd(&s_nf, 1);
                s_fl[w] = tid;
            }
        }
    }
    __syncthreads();

    int nf = s_nf;
    for (int f = 0; f < nf; ++f) {
        int pl = s_fl[f];
        int p = p0 + pl;
        if (tid < 128) {
            const float* xr = X + (size_t)p * NDIM;
            const float* cr = g_cent + tid * NDIM;
            double ac[8] = {0, 0, 0, 0, 0, 0, 0, 0};
            #pragma unroll
            for (int k = 0; k < 16; ++k)
                #pragma unroll
                for (int j = 0; j < 8; ++j)
                    ac[j] += (double)xr[k * 8 + j] * (double)cr[k * 8 + j];
            double dot = ((ac[0] + ac[1]) + (ac[2] + ac[3])) +
                         ((ac[4] + ac[5]) + (ac[6] + ac[7]));
            float dotf = (float)dot;
            float t = sxq[pl] - 2.0f * dotf;
            float d2 = t + scs[tid];
            sD[tid] = d2; sI[tid] = tid;
        }
        __syncthreads();
        #pragma unroll
        for (int o = 64; o; o >>= 1) {
            if (tid < o) {
                float d = sD[tid + o]; int cc = sI[tid + o];
                if (d < sD[tid] || (d == sD[tid] && cc < sI[tid])) {
                    sD[tid] = d; sI[tid] = cc;
                }
            }
            __syncthreads();
        }
        if (tid == 0) g_clusters[p] = sI[0];
        __syncthreads();
    }
}

// ---------------------------------------------------------------------------
// Segment accumulation: EXACT fp32 X reads, THREE private smem accumulator
// groups (race-free +=), 16-point batches per group, fp32 block partials
// merged on write in fixed order (148 partials preserved).
// ---------------------------------------------------------------------------
#define ACCUM_SMEM_BYTES (3 * KCLUST * NDIM * 4 + 3 * KCLUST * 4)

__global__ void __launch_bounds__(384)
accum_kernel(const float* __restrict__ X, int m) {
    if (*(volatile int*)&g_done) return;

    extern __shared__ float sm_f[];                 // 3 x 16384 floats
    int* scnt = (int*)(sm_f + 3 * KCLUST * NDIM);   // 3 x 128 ints

    const int tid = threadIdx.x;
    const int grp = tid >> 7;          // 0 / 1 / 2
    const int dim = tid & 127;
    float* ssum = sm_f + grp * (KCLUST * NDIM);
    int* mycnt = scnt + grp * 128;

    for (int i = tid; i < 3 * KCLUST * NDIM; i += 384) sm_f[i] = 0.0f;
    scnt[tid] = 0;
    __syncthreads();

    int chunk = (m + NBLK_ACC - 1) / NBLK_ACC;
    int lo = blockIdx.x * chunk;
    int hi = lo + chunk; if (hi > m) hi = m;

    int i = lo + grp;
    for (; i + 45 < hi; i += 48) {      // 16 points per group, stride 3
        int cc[16]; float xv[16];
        #pragma unroll
        for (int j = 0; j < 16; ++j) cc[j] = g_clusters[i + 3 * j];
        #pragma unroll
        for (int j = 0; j < 16; ++j)
            xv[j] = X[(size_t)(i + 3 * j) * NDIM + dim];
        if (dim == 0) {
            #pragma unroll
            for (int j = 0; j < 16; ++j) mycnt[cc[j]]++;
        }
        #pragma unroll
        for (int j = 0; j < 16; ++j)
            ssum[cc[j] * NDIM + dim] += xv[j];
    }
    for (; i < hi; i += 3) {
        int c = g_clusters[i];
        float x = X[(size_t)i * NDIM + dim];
        if (dim == 0) mycnt[c]++;
        ssum[c * NDIM + dim] += x;
    }
    __syncthreads();

    float* part = g_part[blockIdx.x];
    for (int k = tid; k < KCLUST * NDIM; k += 384)
        part[k] = (sm_f[k] + sm_f[KCLUST * NDIM + k]) + sm_f[2 * KCLUST * NDIM + k];
    if (tid < 128) {
        int c = (scnt[tid] + scnt[128 + tid]) + scnt[256 + tid];
        if (c) atomicAdd(&g_counts[tid], c);
    }
}

// ---------------------------------------------------------------------------
// Update A: slice-parallel fp64 merge of 148 fp32 partials (1024 threads:
// 8 slices x 128 dims), fp32 divide like reference, convergence votes.
// ---------------------------------------------------------------------------
__global__ void __launch_bounds__(1024)
update_a_kernel(int iter) {
    if (*(volatile int*)&g_done) return;
    int k = blockIdx.x;
    int j = threadIdx.x & 127;
    int s = threadIdx.x >> 7;     // slice 0..7
    int idx = k * NDIM + j;

    const int chunk = (NBLK_ACC + 7) >> 3;   // 19
    int b0 = s * chunk;
    int b1 = b0 + chunk; if (b1 > NBLK_ACC) b1 = NBLK_ACC;

    double a4[4] = {0, 0, 0, 0};
    int b = b0;
    for (; b + 3 < b1; b += 4) {
        #pragma unroll
        for (int u = 0; u < 4; ++u) a4[u] += (double)g_part[b + u][idx];
    }
    for (; b < b1; ++b) a4[0] += (double)g_part[b][idx];
    double accv = (a4[0] + a4[1]) + (a4[2] + a4[3]);

    __shared__ double sdm[1024];
    sdm[threadIdx.x] = accv;
    __syncthreads();
    #pragma unroll
    for (int off = 4; off; off >>= 1) {
        if (s < off) sdm[threadIdx.x] += sdm[threadIdx.x + off * 128];
        __syncthreads();
    }

    __shared__ float rb[128];
    if (threadIdx.x < 128) {
        float sf = (float)sdm[j];
        int cnt = g_counts[k];
        float old = g_cent[idx];
        float newc = (cnt > 0) ? (sf / fmaxf((float)cnt, 1.0f)) : old;
        g_cent_new[idx] = newc;
        float d = newc - old;
        rb[j] = d * d;
    }
    __syncthreads();
    #pragma unroll
    for (int o = 64; o; o >>= 1) {
        if (threadIdx.x < o) rb[threadIdx.x] += rb[threadIdx.x + o];
        __syncthreads();
    }
    if (threadIdx.x == 0) {
        if (rb[0] < 1e-8f) atomicAdd(&g_conv[iter], 1);
        g_counts[k] = 0;
    }
}

// ---------------------------------------------------------------------------
__global__ void __launch_bounds__(128)
update_b_kernel(int iter) {
    if (*(volatile int*)&g_done) return;
    int k = blockIdx.x, j = threadIdx.x;
    int cv = g_conv[iter];
    if (cv == KCLUST) {
        if (k == 0 && j == 0) g_done = 1;
        return;
    }
    int idx = k * NDIM + j;
    float v = g_cent_new[idx];
    g_cent[idx] = v;
    __nv_bfloat16 hi = __float2bfloat16(v);
    g_chi[idx] = hi;
    g_clo[idx] = __float2bfloat16(v - __bfloat162float(hi));

    __shared__ double rb[128];
    rb[j] = (double)v * (double)v;
    __syncthreads();
    #pragma unroll
    for (int o = 64; o; o >>= 1) {
        if (j < o) rb[j] += rb[j + o];
        __syncthreads();
    }
    if (j == 0) g_csqf[k] = (float)rb[0];
}

// ---------------------------------------------------------------------------
__global__ void finalize_kernel(float* __restrict__ out, int m, int out_size) {
    int idx = blockIdx.x * 256 + threadIdx.x;
    const int nc = KCLUST * NDIM;
    if (out_size >= nc + m) {
        if (idx < nc) out[idx] = g_cent[idx];
        else if (idx < nc + m) out[idx] = (float)g_clusters[idx - nc];
    } else if (out_size == m) {
        if (idx < m) out[idx] = (float)g_clusters[idx];
    } else {
        if (idx < out_size && idx < nc) out[idx] = g_cent[idx];
    }
}

// ---------------------------------------------------------------------------
extern "C" void kernel_launch(void* const* d_in, const int* in_sizes, int n_in,
                              void* d_out, int out_size) {
    const float* X  = (const float*)d_in[0];
    const float* C0 = (const float*)d_in[1];
    int m = in_sizes[0] / NDIM;
    if (m > MAX_M) m = MAX_M;

    cudaFuncSetAttribute(assign_tc_kernel,
                         cudaFuncAttributeMaxDynamicSharedMemorySize,
                         ASSIGN_TC_SMEM);
    cudaFuncSetAttribute(accum_kernel,
                         cudaFuncAttributeMaxDynamicSharedMemorySize,
                         ACCUM_SMEM_BYTES);

    init_kernel<<<129, 128>>>(C0);
    xprep_kernel<<<(MAX_M + 7) / 8, 256>>>(X, m);

    int ablocks = (m + 127) / 128;
    for (int it = 0; it < MAXIT; ++it) {
        assign_tc_kernel<<<ablocks, 256, ASSIGN_TC_SMEM>>>(X, m);
        accum_kernel<<<NBLK_ACC, 384, ACCUM_SMEM_BYTES>>>(X, m);
        update_a_kernel<<<128, 1024>>>(it);
        update_b_kernel<<<128, 128>>>(it);
    }

    int fb = (out_size + 255) / 256;
    if (fb < 1) fb = 1;
    finalize_kernel<<<fb, 256>>>((float*)d_out, m, out_size);
}

// round 13
// speedup vs baseline: 1.5148x; 1.0475x over previous
#include <cuda_runtime.h>
#include <cuda_bf16.h>
#include <cfloat>
#include <cstdint>

// ---------------------------------------------------------------------------
// K-means: X [m,128] fp32, centroids_init [128,128] fp32, K=128, 15 iters,
// tol=1e-4. Assignment: fp32 X loaded per k-chunk and split to bf16 hi/lo
// IN-KERNEL (no global xhi/xlo -> X is the only big array and stays
// L2-resident for both assign and accum), 3-combo tensor-core GEMM, fused
// fp64 near-tie refinement. Accum reads exact X (3 groups, 384 thr) into
// 148 fp32 partials; slice-parallel fp64 merge.
// ---------------------------------------------------------------------------

#define KCLUST 128
#define NDIM   128
#define MAXIT  15
#define MAX_M  100352
#define NBLK_ACC 148
#define TAU 4e-3f
#define APITCH 72   // bf16 pitch for 64-col smem tiles (conflict-free ldmatrix)

__device__ float  g_cent[KCLUST * NDIM];
__device__ float  g_cent_new[KCLUST * NDIM];
__device__ float  g_csqf[KCLUST];
__device__ float  g_part[NBLK_ACC][KCLUST * NDIM];
__device__ int    g_counts[KCLUST];
__device__ int    g_clusters[MAX_M];
__device__ float  g_xsq[MAX_M];
__device__ int    g_conv[MAXIT + 1];
__device__ int    g_done;

__device__ __nv_bfloat16 g_chi[KCLUST * NDIM];
__device__ __nv_bfloat16 g_clo[KCLUST * NDIM];

// ---------------------------------------------------------------------------
__global__ void init_kernel(const float* __restrict__ c0) {
    int b = blockIdx.x, t = threadIdx.x;
    if (b < 128) {
        int idx = b * 128 + t;
        float v = c0[idx];
        g_cent[idx] = v;
        __nv_bfloat16 hi = __float2bfloat16(v);
        g_chi[idx] = hi;
        g_clo[idx] = __float2bfloat16(v - __bfloat162float(hi));
        __shared__ double rb[128];
        rb[t] = (double)v * (double)v;
        __syncthreads();
        #pragma unroll
        for (int o = 64; o; o >>= 1) {
            if (t < o) rb[t] += rb[t + o];
            __syncthreads();
        }
        if (t == 0) g_csqf[b] = (float)rb[0];
    } else {
        if (t < KCLUST) g_counts[t] = 0;
        if (t < MAXIT + 1) g_conv[t] = 0;
        if (t == 0) g_done = 0;
    }
}

// ---------------------------------------------------------------------------
// One-time x_sq (fp64 accumulate -> correctly rounded fp32). Warp per row.
// ---------------------------------------------------------------------------
__global__ void __launch_bounds__(256)
xsq_kernel(const float* __restrict__ X, int m) {
    int row = blockIdx.x * 8 + (threadIdx.x >> 5);
    int lane = threadIdx.x & 31;
    if (row >= m) return;
    float4 v = *reinterpret_cast<const float4*>(&X[(size_t)row * NDIM + lane * 4]);
    double s = (double)v.x * v.x + (double)v.y * v.y +
               (double)v.z * v.z + (double)v.w * v.w;
    #pragma unroll
    for (int o = 16; o; o >>= 1) s += __shfl_xor_sync(0xFFFFFFFFu, s, o);
    if (lane == 0) g_xsq[row] = (float)s;
}

// ---------------------------------------------------------------------------
// Assignment: fp32 X -> in-kernel bf16 split -> tensor-core GEMM (3 combos
// per k-chunk: hi*Chi, lo*Chi, hi*Clo), argmin, fused fp64 near-tie refine.
// ---------------------------------------------------------------------------
#define LDSM_X4(r0, r1, r2, r3, addr) \
    asm volatile("ldmatrix.sync.aligned.m8n8.x4.shared.b16 {%0,%1,%2,%3}, [%4];" \
        : "=r"(r0), "=r"(r1), "=r"(r2), "=r"(r3) : "r"(addr))

#define MMA16816(d, a, b0, b1) \
    asm volatile("mma.sync.aligned.m16n8k16.row.col.f32.bf16.bf16.f32 " \
        "{%0,%1,%2,%3},{%4,%5,%6,%7},{%8,%9},{%0,%1,%2,%3};" \
        : "+f"(d[0]), "+f"(d[1]), "+f"(d[2]), "+f"(d[3]) \
        : "r"(a[0]), "r"(a[1]), "r"(a[2]), "r"(a[3]), "r"(b0), "r"(b1))

#define TILE_B (128 * APITCH)
#define TILE_BYTES (TILE_B * 2)
// 4 centroid chunks (chi0, chi1, clo0, clo1) + Ahi + Alo
#define ASSIGN_TC_SMEM (6 * TILE_BYTES + 1024)

__global__ void __launch_bounds__(256, 2)
assign_tc_kernel(const float* __restrict__ X, int m) {
    if (*(volatile int*)&g_done) return;

    extern __shared__ char sm8[];
    __nv_bfloat16* Cs  = (__nv_bfloat16*)sm8;        // 4 centroid chunks
    __nv_bfloat16* Ahi = Cs + 4 * TILE_B;
    __nv_bfloat16* Alo = Ahi + TILE_B;
    float* scs = (float*)(Alo + TILE_B);
    float* sxq = scs + 128;
    float* redD = (float*)sm8;                       // overlays Cs post-GEMM
    int*   redI = (int*)(sm8 + 2048);
    float* redS = (float*)(sm8 + 4096);

    __shared__ int   s_nf;
    __shared__ int   s_fl[128];
    __shared__ float sD[128];
    __shared__ int   sI[128];

    const int tid = threadIdx.x;
    const int lane = tid & 31;
    const int wid = tid >> 5;
    const int wm = wid & 3;
    const int wn = wid >> 2;
    const int p0 = blockIdx.x * 128;

    if (tid == 0) s_nf = 0;
    if (tid < 128) {
        scs[tid] = g_csqf[tid];
        int p = p0 + tid;
        sxq[tid] = (p < m) ? g_xsq[p] : 0.0f;
    }

    // Load 4 centroid chunks: {chi kc0, chi kc64, clo kc0, clo kc64}.
    #pragma unroll
    for (int ch = 0; ch < 4; ++ch) {
        const __nv_bfloat16* Bp = (ch < 2) ? g_chi : g_clo;
        int kc = (ch & 1) * 64;
        #pragma unroll
        for (int i = 0; i < 4; ++i) {
            int lin = tid + i * 256;
            int row = lin >> 3, c8 = lin & 7;
            uint4 vb = *(const uint4*)(Bp + row * 128 + kc + c8 * 8);
            *(uint4*)(Cs + ch * TILE_B + row * APITCH + c8 * 8) = vb;
        }
    }

    const int q = lane >> 3;
    const int r = lane & 7;
    uint32_t asBase = (uint32_t)__cvta_generic_to_shared(Ahi);
    uint32_t csBase = (uint32_t)__cvta_generic_to_shared(Cs);
    uint32_t aoff[2];
    #pragma unroll
    for (int mi = 0; mi < 2; ++mi)
        aoff[mi] = asBase +
            (uint32_t)(((wm * 32 + mi * 16 + (q & 1) * 8 + r) * APITCH + (q >> 1) * 8) * 2);
    uint32_t boff[4];
    #pragma unroll
    for (int nip = 0; nip < 4; ++nip)
        boff[nip] = csBase +
            (uint32_t)(((wn * 64 + nip * 16 + (q >> 1) * 8 + r) * APITCH + (q & 1) * 8) * 2);

    float acc[2][8][4];
    #pragma unroll
    for (int mi = 0; mi < 2; ++mi)
        #pragma unroll
        for (int ni = 0; ni < 8; ++ni)
            #pragma unroll
            for (int u = 0; u < 4; ++u) acc[mi][ni][u] = 0.0f;

    #pragma unroll 1
    for (int s = 0; s < 2; ++s) {
        // Split phase: load X chunk (128 rows x 64 cols fp32), split to
        // Ahi/Alo. Safe to overwrite: first iter after C-load (A unused),
        // second iter after end-of-stage sync below.
        if (s == 0) __syncthreads();
        #pragma unroll
        for (int i = 0; i < 8; ++i) {
            int lin = tid + i * 256;
            int row = lin >> 4, c16 = lin & 15;
            int prow = p0 + row; if (prow >= m) prow = m - 1;
            uint4 v = *(const uint4*)(X + (size_t)prow * NDIM + s * 64 + c16 * 4);
            const float* fp = (const float*)&v;
            __nv_bfloat16 h[4], l[4];
            #pragma unroll
            for (int j = 0; j < 4; ++j) {
                h[j] = __float2bfloat16(fp[j]);
                l[j] = __float2bfloat16(fp[j] - __bfloat162float(h[j]));
            }
            __nv_bfloat162* hp = (__nv_bfloat162*)(Ahi + row * APITCH + c16 * 4);
            __nv_bfloat162* lp = (__nv_bfloat162*)(Alo + row * APITCH + c16 * 4);
            hp[0] = __nv_bfloat162(h[0], h[1]); hp[1] = __nv_bfloat162(h[2], h[3]);
            lp[0] = __nv_bfloat162(l[0], l[1]); lp[1] = __nv_bfloat162(l[2], l[3]);
        }
        __syncthreads();

        const uint32_t chiB = (uint32_t)s * TILE_BYTES;
        const uint32_t cloB = (uint32_t)(2 + s) * TILE_BYTES;

        #pragma unroll
        for (int ks = 0; ks < 4; ++ks) {
            uint32_t ah[2][4], al[2][4];
            #pragma unroll
            for (int mi = 0; mi < 2; ++mi) {
                LDSM_X4(ah[mi][0], ah[mi][1], ah[mi][2], ah[mi][3],
                        aoff[mi] + ks * 32);
                LDSM_X4(al[mi][0], al[mi][1], al[mi][2], al[mi][3],
                        aoff[mi] + TILE_BYTES + ks * 32);
            }
            uint32_t b[4][4];
            #pragma unroll
            for (int nip = 0; nip < 4; ++nip)
                LDSM_X4(b[nip][0], b[nip][1], b[nip][2], b[nip][3],
                        boff[nip] + chiB + ks * 32);
            #pragma unroll
            for (int mi = 0; mi < 2; ++mi)
                #pragma unroll
                for (int nip = 0; nip < 4; ++nip) {
                    MMA16816(acc[mi][nip * 2 + 0], ah[mi], b[nip][0], b[nip][1]);
                    MMA16816(acc[mi][nip * 2 + 1], ah[mi], b[nip][2], b[nip][3]);
                    MMA16816(acc[mi][nip * 2 + 0], al[mi], b[nip][0], b[nip][1]);
                    MMA16816(acc[mi][nip * 2 + 1], al[mi], b[nip][2], b[nip][3]);
                }
            #pragma unroll
            for (int nip = 0; nip < 4; ++nip)
                LDSM_X4(b[nip][0], b[nip][1], b[nip][2], b[nip][3],
                        boff[nip] + cloB + ks * 32);
            #pragma unroll
            for (int mi = 0; mi < 2; ++mi)
                #pragma unroll
                for (int nip = 0; nip < 4; ++nip) {
                    MMA16816(acc[mi][nip * 2 + 0], ah[mi], b[nip][0], b[nip][1]);
                    MMA16816(acc[mi][nip * 2 + 1], ah[mi], b[nip][2], b[nip][3]);
                }
        }
        __syncthreads();   // all warps done reading Ahi/Alo before next split
    }

    // Epilogue: d2 + best/second-best per point.
    const int r0 = lane >> 2;
    const int c0 = (lane & 3) * 2;
    float bd[4], sd[4]; int bi[4];
    #pragma unroll
    for (int mi = 0; mi < 2; ++mi) {
        #pragma unroll
        for (int h = 0; h < 2; ++h) {
            int qq = mi * 2 + h;
            int pl = wm * 32 + mi * 16 + h * 8 + r0;
            float xq = sxq[pl];
            float b_ = FLT_MAX, s_ = FLT_MAX; int i_ = 0;
            #pragma unroll
            for (int ni = 0; ni < 8; ++ni) {
                #pragma unroll
                for (int u = 0; u < 2; ++u) {
                    int n = wn * 64 + ni * 8 + c0 + u;
                    float d2 = (xq - 2.0f * acc[mi][ni][h * 2 + u]) + scs[n];
                    if (d2 < b_) { s_ = b_; b_ = d2; i_ = n; }
                    else if (d2 < s_) s_ = d2;
                }
            }
            bd[qq] = b_; sd[qq] = s_; bi[qq] = i_;
        }
    }
    #pragma unroll
    for (int off = 1; off <= 2; off <<= 1) {
        #pragma unroll
        for (int qq = 0; qq < 4; ++qq) {
            float obd = __shfl_xor_sync(0xFFFFFFFFu, bd[qq], off);
            int   obi = __shfl_xor_sync(0xFFFFFFFFu, bi[qq], off);
            float osd = __shfl_xor_sync(0xFFFFFFFFu, sd[qq], off);
            bool take = (obd < bd[qq]) || (obd == bd[qq] && obi < bi[qq]);
            float loser = take ? bd[qq] : obd;
            sd[qq] = fminf(fminf(sd[qq], osd), loser);
            if (take) { bd[qq] = obd; bi[qq] = obi; }
        }
    }
    if ((lane & 3) == 0) {
        #pragma unroll
        for (int qq = 0; qq < 4; ++qq) {
            int pl = wm * 32 + (qq >> 1) * 16 + (qq & 1) * 8 + r0;
            redD[pl * 2 + wn] = bd[qq];
            redI[pl * 2 + wn] = bi[qq];
            redS[pl * 2 + wn] = sd[qq];
        }
    }
    __syncthreads();

    if (tid < 128) {
        int p = p0 + tid;
        if (p < m) {
            float b_ = redD[tid * 2], s_ = redS[tid * 2];
            int i_ = redI[tid * 2];
            float od = redD[tid * 2 + 1], os = redS[tid * 2 + 1];
            int oi = redI[tid * 2 + 1];
            bool take = (od < b_) || (od == b_ && oi < i_);
            float loser = take ? b_ : od;
            s_ = fminf(fminf(s_, os), loser);
            if (take) { b_ = od; i_ = oi; }
            g_clusters[p] = i_;
            if (s_ - b_ < TAU) {
                int w = atomicAdd(&s_nf, 1);
                s_fl[w] = tid;
            }
        }
    }
    __syncthreads();

    // Fused near-tie refinement: fp64 dot, reference fp32 op order, first-wins.
    int nf = s_nf;
    for (int f = 0; f < nf; ++f) {
        int pl = s_fl[f];
        int p = p0 + pl;
        if (tid < 128) {
            const float* xr = X + (size_t)p * NDIM;
            const float* cr = g_cent + tid * NDIM;
            double ac[8] = {0, 0, 0, 0, 0, 0, 0, 0};
            #pragma unroll
            for (int k = 0; k < 16; ++k)
                #pragma unroll
                for (int j = 0; j < 8; ++j)
                    ac[j] += (double)xr[k * 8 + j] * (double)cr[k * 8 + j];
            double dot = ((ac[0] + ac[1]) + (ac[2] + ac[3])) +
                         ((ac[4] + ac[5]) + (ac[6] + ac[7]));
            float dotf = (float)dot;
            float t = sxq[pl] - 2.0f * dotf;
            float d2 = t + scs[tid];
            sD[tid] = d2; sI[tid] = tid;
        }
        __syncthreads();
        #pragma unroll
        for (int o = 64; o; o >>= 1) {
            if (tid < o) {
                float d = sD[tid + o]; int cc = sI[tid + o];
                if (d < sD[tid] || (d == sD[tid] && cc < sI[tid])) {
                    sD[tid] = d; sI[tid] = cc;
                }
            }
            __syncthreads();
        }
        if (tid == 0) g_clusters[p] = sI[0];
        __syncthreads();
    }
}

// ---------------------------------------------------------------------------
// Segment accumulation: EXACT fp32 X reads (L2-resident now), THREE private
// smem accumulator groups, 16-point batches per group, fp32 block partials
// merged on write in fixed order (148 partials).
// ---------------------------------------------------------------------------
#define ACCUM_SMEM_BYTES (3 * KCLUST * NDIM * 4 + 3 * KCLUST * 4)

__global__ void __launch_bounds__(384)
accum_kernel(const float* __restrict__ X, int m) {
    if (*(volatile int*)&g_done) return;

    extern __shared__ float sm_f[];                 // 3 x 16384 floats
    int* scnt = (int*)(sm_f + 3 * KCLUST * NDIM);   // 3 x 128 ints

    const int tid = threadIdx.x;
    const int grp = tid >> 7;          // 0 / 1 / 2
    const int dim = tid & 127;
    float* ssum = sm_f + grp * (KCLUST * NDIM);
    int* mycnt = scnt + grp * 128;

    for (int i = tid; i < 3 * KCLUST * NDIM; i += 384) sm_f[i] = 0.0f;
    scnt[tid] = 0;
    __syncthreads();

    int chunk = (m + NBLK_ACC - 1) / NBLK_ACC;
    int lo = blockIdx.x * chunk;
    int hi = lo + chunk; if (hi > m) hi = m;

    int i = lo + grp;
    for (; i + 45 < hi; i += 48) {      // 16 points per group, stride 3
        int cc[16]; float xv[16];
        #pragma unroll
        for (int j = 0; j < 16; ++j) cc[j] = g_clusters[i + 3 * j];
        #pragma unroll
        for (int j = 0; j < 16; ++j)
            xv[j] = X[(size_t)(i + 3 * j) * NDIM + dim];
        if (dim == 0) {
            #pragma unroll
            for (int j = 0; j < 16; ++j) mycnt[cc[j]]++;
        }
        #pragma unroll
        for (int j = 0; j < 16; ++j)
            ssum[cc[j] * NDIM + dim] += xv[j];
    }
    for (; i < hi; i += 3) {
        int c = g_clusters[i];
        float x = X[(size_t)i * NDIM + dim];
        if (dim == 0) mycnt[c]++;
        ssum[c * NDIM + dim] += x;
    }
    __syncthreads();

    float* part = g_part[blockIdx.x];
    for (int k = tid; k < KCLUST * NDIM; k += 384)
        part[k] = (sm_f[k] + sm_f[KCLUST * NDIM + k]) + sm_f[2 * KCLUST * NDIM + k];
    if (tid < 128) {
        int c = (scnt[tid] + scnt[128 + tid]) + scnt[256 + tid];
        if (c) atomicAdd(&g_counts[tid], c);
    }
}

// ---------------------------------------------------------------------------
// Update A: slice-parallel fp64 merge of 148 fp32 partials (1024 threads:
// 8 slices x 128 dims), fp32 divide like reference, convergence votes.
// ---------------------------------------------------------------------------
__global__ void __launch_bounds__(1024)
update_a_kernel(int iter) {
    if (*(volatile int*)&g_done) return;
    int k = blockIdx.x;
    int j = threadIdx.x & 127;
    int s = threadIdx.x >> 7;     // slice 0..7
    int idx = k * NDIM + j;

    const int chunk = (NBLK_ACC + 7) >> 3;   // 19
    int b0 = s * chunk;
    int b1 = b0 + chunk; if (b1 > NBLK_ACC) b1 = NBLK_ACC;

    double a4[4] = {0, 0, 0, 0};
    int b = b0;
    for (; b + 3 < b1; b += 4) {
        #pragma unroll
        for (int u = 0; u < 4; ++u) a4[u] += (double)g_part[b + u][idx];
    }
    for (; b < b1; ++b) a4[0] += (double)g_part[b][idx];
    double accv = (a4[0] + a4[1]) + (a4[2] + a4[3]);

    __shared__ double sdm[1024];
    sdm[threadIdx.x] = accv;
    __syncthreads();
    #pragma unroll
    for (int off = 4; off; off >>= 1) {
        if (s < off) sdm[threadIdx.x] += sdm[threadIdx.x + off * 128];
        __syncthreads();
    }

    __shared__ float rb[128];
    if (threadIdx.x < 128) {
        float sf = (float)sdm[j];
        int cnt = g_counts[k];
        float old = g_cent[idx];
        float newc = (cnt > 0) ? (sf / fmaxf((float)cnt, 1.0f)) : old;
        g_cent_new[idx] = newc;
        float d = newc - old;
        rb[j] = d * d;
    }
    __syncthreads();
    #pragma unroll
    for (int o = 64; o; o >>= 1) {
        if (threadIdx.x < o) rb[threadIdx.x] += rb[threadIdx.x + o];
        __syncthreads();
    }
    if (threadIdx.x == 0) {
        if (rb[0] < 1e-8f) atomicAdd(&g_conv[iter], 1);
        g_counts[k] = 0;
    }
}

// ---------------------------------------------------------------------------
__global__ void __launch_bounds__(128)
update_b_kernel(int iter) {
    if (*(volatile int*)&g_done) return;
    int k = blockIdx.x, j = threadIdx.x;
    int cv = g_conv[iter];
    if (cv == KCLUST) {
        if (k == 0 && j == 0) g_done = 1;
        return;
    }
    int idx = k * NDIM + j;
    float v = g_cent_new[idx];
    g_cent[idx] = v;
    __nv_bfloat16 hi = __float2bfloat16(v);
    g_chi[idx] = hi;
    g_clo[idx] = __float2bfloat16(v - __bfloat162float(hi));

    __shared__ double rb[128];
    rb[j] = (double)v * (double)v;
    __syncthreads();
    #pragma unroll
    for (int o = 64; o; o >>= 1) {
        if (j < o) rb[j] += rb[j + o];
        __syncthreads();
    }
    if (j == 0) g_csqf[k] = (float)rb[0];
}

// ---------------------------------------------------------------------------
__global__ void finalize_kernel(float* __restrict__ out, int m, int out_size) {
    int idx = blockIdx.x * 256 + threadIdx.x;
    const int nc = KCLUST * NDIM;
    if (out_size >= nc + m) {
        if (idx < nc) out[idx] = g_cent[idx];
        else if (idx < nc + m) out[idx] = (float)g_clusters[idx - nc];
    } else if (out_size == m) {
        if (idx < m) out[idx] = (float)g_clusters[idx];
    } else {
        if (idx < out_size && idx < nc) out[idx] = g_cent[idx];
    }
}

// ---------------------------------------------------------------------------
extern "C" void kernel_launch(void* const* d_in, const int* in_sizes, int n_in,
                              void* d_out, int out_size) {
    const float* X  = (const float*)d_in[0];
    const float* C0 = (const float*)d_in[1];
    int m = in_sizes[0] / NDIM;
    if (m > MAX_M) m = MAX_M;

    cudaFuncSetAttribute(assign_tc_kernel,
                         cudaFuncAttributeMaxDynamicSharedMemorySize,
                         ASSIGN_TC_SMEM);
    cudaFuncSetAttribute(accum_kernel,
                         cudaFuncAttributeMaxDynamicSharedMemorySize,
                         ACCUM_SMEM_BYTES);

    init_kernel<<<129, 128>>>(C0);
    xsq_kernel<<<(m + 7) / 8, 256>>>(X, m);

    int ablocks = (m + 127) / 128;
    for (int it = 0; it < MAXIT; ++it) {
        assign_tc_kernel<<<ablocks, 256, ASSIGN_TC_SMEM>>>(X, m);
        accum_kernel<<<NBLK_ACC, 384, ACCUM_SMEM_BYTES>>>(X, m);
        update_a_kernel<<<128, 1024>>>(it);
        update_b_kernel<<<128, 128>>>(it);
    }

    int fb = (out_size + 255) / 256;
    if (fb < 1) fb = 1;
    finalize_kernel<<<fb, 256>>>((float*)d_out, m, out_size);
}

// round 15
// speedup vs baseline: 1.6009x; 1.0569x over previous
#include <cuda_runtime.h>
#include <cuda_bf16.h>
#include <cfloat>
#include <cstdint>

// ---------------------------------------------------------------------------
// K-means: X [m,128] fp32, centroids_init [128,128] fp32, K=128, 15 iters,
// tol=1e-4. NOTE: tcgen05 is NOT available (harness ptxas targets sm_103
// without the 'a' feature set) — assignment uses mma.sync (HMMA) with an
// in-kernel bf16 hi/lo split of X (X stays the only big array, L2-resident),
// 16 warps x (16x64) tiles for issue occupancy, fused fp64 near-tie
// refinement replaying the reference fp32 op order. Accum reads exact X
// (3 groups) into 148 fp32 partials; slice-parallel fp64 merge.
// ---------------------------------------------------------------------------

#define KCLUST 128
#define NDIM   128
#define MAXIT  15
#define MAX_M  100352
#define NBLK_ACC 148
#define TAU 4e-3f
#define APITCH 72   // bf16 pitch for 64-col smem tiles (conflict-free ldmatrix)

__device__ float  g_cent[KCLUST * NDIM];
__device__ float  g_cent_new[KCLUST * NDIM];
__device__ float  g_csqf[KCLUST];
__device__ float  g_part[NBLK_ACC][KCLUST * NDIM];
__device__ int    g_counts[KCLUST];
__device__ int    g_clusters[MAX_M];
__device__ float  g_xsq[MAX_M];
__device__ int    g_conv[MAXIT + 1];
__device__ int    g_done;

__device__ __nv_bfloat16 g_chi[KCLUST * NDIM];
__device__ __nv_bfloat16 g_clo[KCLUST * NDIM];

// ---------------------------------------------------------------------------
__global__ void init_kernel(const float* __restrict__ c0) {
    int b = blockIdx.x, t = threadIdx.x;
    if (b < 128) {
        int idx = b * 128 + t;
        float v = c0[idx];
        g_cent[idx] = v;
        __nv_bfloat16 hi = __float2bfloat16(v);
        g_chi[idx] = hi;
        g_clo[idx] = __float2bfloat16(v - __bfloat162float(hi));
        __shared__ double rb[128];
        rb[t] = (double)v * (double)v;
        __syncthreads();
        #pragma unroll
        for (int o = 64; o; o >>= 1) {
            if (t < o) rb[t] += rb[t + o];
            __syncthreads();
        }
        if (t == 0) g_csqf[b] = (float)rb[0];
    } else {
        if (t < KCLUST) g_counts[t] = 0;
        if (t < MAXIT + 1) g_conv[t] = 0;
        if (t == 0) g_done = 0;
    }
}

// ---------------------------------------------------------------------------
__global__ void __launch_bounds__(256)
xsq_kernel(const float* __restrict__ X, int m) {
    int row = blockIdx.x * 8 + (threadIdx.x >> 5);
    int lane = threadIdx.x & 31;
    if (row >= m) return;
    float4 v = *reinterpret_cast<const float4*>(&X[(size_t)row * NDIM + lane * 4]);
    double s = (double)v.x * v.x + (double)v.y * v.y +
               (double)v.z * v.z + (double)v.w * v.w;
    #pragma unroll
    for (int o = 16; o; o >>= 1) s += __shfl_xor_sync(0xFFFFFFFFu, s, o);
    if (lane == 0) g_xsq[row] = (float)s;
}

// ---------------------------------------------------------------------------
// Assignment: fp32 X -> in-kernel bf16 split -> mma.sync GEMM (3 combos per
// k-chunk: hi*Chi, lo*Chi, hi*Clo), 16 warps x (16M x 64N) tiles, argmin,
// fused fp64 near-tie refinement.
// ---------------------------------------------------------------------------
#define LDSM_X4(r0, r1, r2, r3, addr) \
    asm volatile("ldmatrix.sync.aligned.m8n8.x4.shared.b16 {%0,%1,%2,%3}, [%4];" \
        : "=r"(r0), "=r"(r1), "=r"(r2), "=r"(r3) : "r"(addr))

#define MMA16816(d, a, b0, b1) \
    asm volatile("mma.sync.aligned.m16n8k16.row.col.f32.bf16.bf16.f32 " \
        "{%0,%1,%2,%3},{%4,%5,%6,%7},{%8,%9},{%0,%1,%2,%3};" \
        : "+f"(d[0]), "+f"(d[1]), "+f"(d[2]), "+f"(d[3]) \
        : "r"(a[0]), "r"(a[1]), "r"(a[2]), "r"(a[3]), "r"(b0), "r"(b1))

#define TILE_B (128 * APITCH)
#define TILE_BYTES (TILE_B * 2)
// 4 centroid chunks (chi0, chi1, clo0, clo1) + Ahi + Alo
#define ASSIGN_TC_SMEM (6 * TILE_BYTES + 1024)

__global__ void __launch_bounds__(512, 2)
assign_tc_kernel(const float* __restrict__ X, int m) {
    if (*(volatile int*)&g_done) return;

    extern __shared__ char sm8[];
    __nv_bfloat16* Cs  = (__nv_bfloat16*)sm8;        // 4 centroid chunks
    __nv_bfloat16* Ahi = Cs + 4 * TILE_B;
    __nv_bfloat16* Alo = Ahi + TILE_B;
    float* scs = (float*)(Alo + TILE_B);
    float* sxq = scs + 128;
    float* redD = (float*)sm8;                       // overlays Cs post-GEMM
    int*   redI = (int*)(sm8 + 2048);
    float* redS = (float*)(sm8 + 4096);

    __shared__ int   s_nf;
    __shared__ int   s_fl[128];
    __shared__ float sD[128];
    __shared__ int   sI[128];

    const int tid = threadIdx.x;
    const int lane = tid & 31;
    const int wid = tid >> 5;      // 0..15
    const int wn = wid & 1;        // N tile (64 cols)
    const int wm = wid >> 1;       // M tile (16 rows), 0..7
    const int p0 = blockIdx.x * 128;

    if (tid == 0) s_nf = 0;
    if (tid < 128) {
        scs[tid] = g_csqf[tid];
        int p = p0 + tid;
        sxq[tid] = (p < m) ? g_xsq[p] : 0.0f;
    }

    // Load 4 centroid chunks: {chi kc0, chi kc64, clo kc0, clo kc64}.
    #pragma unroll
    for (int ch = 0; ch < 4; ++ch) {
        const __nv_bfloat16* Bp = (ch < 2) ? g_chi : g_clo;
        int kc = (ch & 1) * 64;
        #pragma unroll
        for (int i = 0; i < 2; ++i) {
            int lin = tid + i * 512;               // 0..1023 uint4
            int row = lin >> 3, c8 = lin & 7;
            uint4 vb = *(const uint4*)(Bp + row * 128 + kc + c8 * 8);
            *(uint4*)(Cs + ch * TILE_B + row * APITCH + c8 * 8) = vb;
        }
    }

    const int q = lane >> 3;
    const int r = lane & 7;
    uint32_t asBase = (uint32_t)__cvta_generic_to_shared(Ahi);
    uint32_t csBase = (uint32_t)__cvta_generic_to_shared(Cs);
    uint32_t aoff = asBase +
        (uint32_t)(((wm * 16 + (q & 1) * 8 + r) * APITCH + (q >> 1) * 8) * 2);
    uint32_t boff[4];
    #pragma unroll
    for (int nip = 0; nip < 4; ++nip)
        boff[nip] = csBase +
            (uint32_t)(((wn * 64 + nip * 16 + (q >> 1) * 8 + r) * APITCH + (q & 1) * 8) * 2);

    float acc[8][4];
    #pragma unroll
    for (int ni = 0; ni < 8; ++ni)
        #pragma unroll
        for (int u = 0; u < 4; ++u) acc[ni][u] = 0.0f;

    #pragma unroll 1
    for (int s = 0; s < 2; ++s) {
        // Split phase: load X chunk (128 rows x 64 cols fp32), split to Ahi/Alo.
        if (s == 0) __syncthreads();
        #pragma unroll
        for (int i = 0; i < 4; ++i) {
            int lin = tid + i * 512;               // 0..2047 uint4
            int row = lin >> 4, c16 = lin & 15;
            int prow = p0 + row; if (prow >= m) prow = m - 1;
            uint4 v = *(const uint4*)(X + (size_t)prow * NDIM + s * 64 + c16 * 4);
            const float* fp = (const float*)&v;
            __nv_bfloat16 h[4], l[4];
            #pragma unroll
            for (int j = 0; j < 4; ++j) {
                h[j] = __float2bfloat16(fp[j]);
                l[j] = __float2bfloat16(fp[j] - __bfloat162float(h[j]));
            }
            __nv_bfloat162* hp = (__nv_bfloat162*)(Ahi + row * APITCH + c16 * 4);
            __nv_bfloat162* lp = (__nv_bfloat162*)(Alo + row * APITCH + c16 * 4);
            hp[0] = __nv_bfloat162(h[0], h[1]); hp[1] = __nv_bfloat162(h[2], h[3]);
            lp[0] = __nv_bfloat162(l[0], l[1]); lp[1] = __nv_bfloat162(l[2], l[3]);
        }
        __syncthreads();

        const uint32_t chiB = (uint32_t)s * TILE_BYTES;
        const uint32_t cloB = (uint32_t)(2 + s) * TILE_BYTES;

        #pragma unroll
        for (int ks = 0; ks < 4; ++ks) {
            uint32_t ah[4], al[4];
            LDSM_X4(ah[0], ah[1], ah[2], ah[3], aoff + ks * 32);
            LDSM_X4(al[0], al[1], al[2], al[3], aoff + TILE_BYTES + ks * 32);
            uint32_t b[4][4];
            #pragma unroll
            for (int nip = 0; nip < 4; ++nip)
                LDSM_X4(b[nip][0], b[nip][1], b[nip][2], b[nip][3],
                        boff[nip] + chiB + ks * 32);
            #pragma unroll
            for (int nip = 0; nip < 4; ++nip) {
                MMA16816(acc[nip * 2 + 0], ah, b[nip][0], b[nip][1]);
                MMA16816(acc[nip * 2 + 1], ah, b[nip][2], b[nip][3]);
                MMA16816(acc[nip * 2 + 0], al, b[nip][0], b[nip][1]);
                MMA16816(acc[nip * 2 + 1], al, b[nip][2], b[nip][3]);
            }
            #pragma unroll
            for (int nip = 0; nip < 4; ++nip)
                LDSM_X4(b[nip][0], b[nip][1], b[nip][2], b[nip][3],
                        boff[nip] + cloB + ks * 32);
            #pragma unroll
            for (int nip = 0; nip < 4; ++nip) {
                MMA16816(acc[nip * 2 + 0], ah, b[nip][0], b[nip][1]);
                MMA16816(acc[nip * 2 + 1], ah, b[nip][2], b[nip][3]);
            }
        }
        __syncthreads();   // all warps done reading Ahi/Alo before next split
    }

    // Epilogue: d2 + best/second-best per point (warp covers 16 rows x 64 cols).
    const int r0 = lane >> 2;
    const int c0 = (lane & 3) * 2;
    float bd[2], sd[2]; int bi[2];
    #pragma unroll
    for (int h = 0; h < 2; ++h) {
        int pl = wm * 16 + h * 8 + r0;
        float xq = sxq[pl];
        float b_ = FLT_MAX, s_ = FLT_MAX; int i_ = 0;
        #pragma unroll
        for (int ni = 0; ni < 8; ++ni) {
            #pragma unroll
            for (int u = 0; u < 2; ++u) {
                int n = wn * 64 + ni * 8 + c0 + u;
                float d2 = (xq - 2.0f * acc[ni][h * 2 + u]) + scs[n];
                if (d2 < b_) { s_ = b_; b_ = d2; i_ = n; }
                else if (d2 < s_) s_ = d2;
            }
        }
        bd[h] = b_; sd[h] = s_; bi[h] = i_;
    }
    #pragma unroll
    for (int off = 1; off <= 2; off <<= 1) {
        #pragma unroll
        for (int h = 0; h < 2; ++h) {
            float obd = __shfl_xor_sync(0xFFFFFFFFu, bd[h], off);
            int   obi = __shfl_xor_sync(0xFFFFFFFFu, bi[h], off);
            float osd = __shfl_xor_sync(0xFFFFFFFFu, sd[h], off);
            bool take = (obd < bd[h]) || (obd == bd[h] && obi < bi[h]);
            float loser = take ? bd[h] : obd;
            sd[h] = fminf(fminf(sd[h], osd), loser);
            if (take) { bd[h] = obd; bi[h] = obi; }
        }
    }
    if ((lane & 3) == 0) {
        #pragma unroll
        for (int h = 0; h < 2; ++h) {
            int pl = wm * 16 + h * 8 + r0;
            redD[pl * 2 + wn] = bd[h];
            redI[pl * 2 + wn] = bi[h];
            redS[pl * 2 + wn] = sd[h];
        }
    }
    __syncthreads();

    if (tid < 128) {
        int p = p0 + tid;
        if (p < m) {
            float b_ = redD[tid * 2], s_ = redS[tid * 2];
            int i_ = redI[tid * 2];
            float od = redD[tid * 2 + 1], os = redS[tid * 2 + 1];
            int oi = redI[tid * 2 + 1];
            bool take = (od < b_) || (od == b_ && oi < i_);
            float loser = take ? b_ : od;
            s_ = fminf(fminf(s_, os), loser);
            if (take) { b_ = od; i_ = oi; }
            g_clusters[p] = i_;
            if (s_ - b_ < TAU) {
                int w = atomicAdd(&s_nf, 1);
                s_fl[w] = tid;
            }
        }
    }
    __syncthreads();

    // Fused near-tie refinement: fp64 dot, reference fp32 op order, first-wins.
    int nf = s_nf;
    for (int f = 0; f < nf; ++f) {
        int pl = s_fl[f];
        int p = p0 + pl;
        if (tid < 128) {
            const float* xr = X + (size_t)p * NDIM;
            const float* cr = g_cent + tid * NDIM;
            double ac[8] = {0, 0, 0, 0, 0, 0, 0, 0};
            #pragma unroll
            for (int k = 0; k < 16; ++k)
                #pragma unroll
                for (int j = 0; j < 8; ++j)
                    ac[j] += (double)xr[k * 8 + j] * (double)cr[k * 8 + j];
            double dot = ((ac[0] + ac[1]) + (ac[2] + ac[3])) +
                         ((ac[4] + ac[5]) + (ac[6] + ac[7]));
            float dotf = (float)dot;
            float t = sxq[pl] - 2.0f * dotf;
            float d2 = t + scs[tid];
            sD[tid] = d2; sI[tid] = tid;
        }
        __syncthreads();
        #pragma unroll
        for (int o = 64; o; o >>= 1) {
            if (tid < o) {
                float d = sD[tid + o]; int cc = sI[tid + o];
                if (d < sD[tid] || (d == sD[tid] && cc < sI[tid])) {
                    sD[tid] = d; sI[tid] = cc;
                }
            }
            __syncthreads();
        }
        if (tid == 0) g_clusters[p] = sI[0];
        __syncthreads();
    }
}

// ---------------------------------------------------------------------------
// Segment accumulation: EXACT fp32 X reads, THREE private smem accumulator
// groups, 16-point batches per group, fp32 block partials (148).
// ---------------------------------------------------------------------------
#define ACCUM_SMEM_BYTES (3 * KCLUST * NDIM * 4 + 3 * KCLUST * 4)

__global__ void __launch_bounds__(384)
accum_kernel(const float* __restrict__ X, int m) {
    if (*(volatile int*)&g_done) return;

    extern __shared__ float sm_f[];
    int* scnt = (int*)(sm_f + 3 * KCLUST * NDIM);

    const int tid = threadIdx.x;
    const int grp = tid >> 7;
    const int dim = tid & 127;
    float* ssum = sm_f + grp * (KCLUST * NDIM);
    int* mycnt = scnt + grp * 128;

    for (int i = tid; i < 3 * KCLUST * NDIM; i += 384) sm_f[i] = 0.0f;
    scnt[tid] = 0;
    __syncthreads();

    int chunk = (m + NBLK_ACC - 1) / NBLK_ACC;
    int lo = blockIdx.x * chunk;
    int hi = lo + chunk; if (hi > m) hi = m;

    int i = lo + grp;
    for (; i + 45 < hi; i += 48) {
        int cc[16]; float xv[16];
        #pragma unroll
        for (int j = 0; j < 16; ++j) cc[j] = g_clusters[i + 3 * j];
        #pragma unroll
        for (int j = 0; j < 16; ++j)
            xv[j] = X[(size_t)(i + 3 * j) * NDIM + dim];
        if (dim == 0) {
            #pragma unroll
            for (int j = 0; j < 16; ++j) mycnt[cc[j]]++;
        }
        #pragma unroll
        for (int j = 0; j < 16; ++j)
            ssum[cc[j] * NDIM + dim] += xv[j];
    }
    for (; i < hi; i += 3) {
        int c = g_clusters[i];
        float x = X[(size_t)i * NDIM + dim];
        if (dim == 0) mycnt[c]++;
        ssum[c * NDIM + dim] += x;
    }
    __syncthreads();

    float* part = g_part[blockIdx.x];
    for (int k = tid; k < KCLUST * NDIM; k += 384)
        part[k] = (sm_f[k] + sm_f[KCLUST * NDIM + k]) + sm_f[2 * KCLUST * NDIM + k];
    if (tid < 128) {
        int c = (scnt[tid] + scnt[128 + tid]) + scnt[256 + tid];
        if (c) atomicAdd(&g_counts[tid], c);
    }
}

// ---------------------------------------------------------------------------
// Update A: slice-parallel fp64 merge of 148 fp32 partials (1024 threads:
// 8 slices x 128 dims), fp32 divide like reference, convergence votes.
// ---------------------------------------------------------------------------
__global__ void __launch_bounds__(1024)
update_a_kernel(int iter) {
    if (*(volatile int*)&g_done) return;
    int k = blockIdx.x;
    int j = threadIdx.x & 127;
    int s = threadIdx.x >> 7;
    int idx = k * NDIM + j;

    const int chunk = (NBLK_ACC + 7) >> 3;
    int b0 = s * chunk;
    int b1 = b0 + chunk; if (b1 > NBLK_ACC) b1 = NBLK_ACC;

    double a4[4] = {0, 0, 0, 0};
    int b = b0;
    for (; b + 3 < b1; b += 4) {
        #pragma unroll
        for (int u = 0; u < 4; ++u) a4[u] += (double)g_part[b + u][idx];
    }
    for (; b < b1; ++b) a4[0] += (double)g_part[b][idx];
    double accv = (a4[0] + a4[1]) + (a4[2] + a4[3]);

    __shared__ double sdm[1024];
    sdm[threadIdx.x] = accv;
    __syncthreads();
    #pragma unroll
    for (int off = 4; off; off >>= 1) {
        if (s < off) sdm[threadIdx.x] += sdm[threadIdx.x + off * 128];
        __syncthreads();
    }

    __shared__ float rb[128];
    if (threadIdx.x < 128) {
        float sf = (float)sdm[j];
        int cnt = g_counts[k];
        float old = g_cent[idx];
        float newc = (cnt > 0) ? (sf / fmaxf((float)cnt, 1.0f)) : old;
        g_cent_new[idx] = newc;
        float d = newc - old;
        rb[j] = d * d;
    }
    __syncthreads();
    #pragma unroll
    for (int o = 64; o; o >>= 1) {
        if (threadIdx.x < o) rb[threadIdx.x] += rb[threadIdx.x + o];
        __syncthreads();
    }
    if (threadIdx.x == 0) {
        if (rb[0] < 1e-8f) atomicAdd(&g_conv[iter], 1);
        g_counts[k] = 0;
    }
}

// ---------------------------------------------------------------------------
__global__ void __launch_bounds__(128)
update_b_kernel(int iter) {
    if (*(volatile int*)&g_done) return;
    int k = blockIdx.x, j = threadIdx.x;
    int cv = g_conv[iter];
    if (cv == KCLUST) {
        if (k == 0 && j == 0) g_done = 1;
        return;
    }
    int idx = k * NDIM + j;
    float v = g_cent_new[idx];
    g_cent[idx] = v;
    __nv_bfloat16 hi = __float2bfloat16(v);
    g_chi[idx] = hi;
    g_clo[idx] = __float2bfloat16(v - __bfloat162float(hi));

    __shared__ double rb[128];
    rb[j] = (double)v * (double)v;
    __syncthreads();
    #pragma unroll
    for (int o = 64; o; o >>= 1) {
        if (j < o) rb[j] += rb[j + o];
        __syncthreads();
    }
    if (j == 0) g_csqf[k] = (float)rb[0];
}

// ---------------------------------------------------------------------------
__global__ void finalize_kernel(float* __restrict__ out, int m, int out_size) {
    int idx = blockIdx.x * 256 + threadIdx.x;
    const int nc = KCLUST * NDIM;
    if (out_size >= nc + m) {
        if (idx < nc) out[idx] = g_cent[idx];
        else if (idx < nc + m) out[idx] = (float)g_clusters[idx - nc];
    } else if (out_size == m) {
        if (idx < m) out[idx] = (float)g_clusters[idx];
    } else {
        if (idx < out_size && idx < nc) out[idx] = g_cent[idx];
    }
}

// ---------------------------------------------------------------------------
extern "C" void kernel_launch(void* const* d_in, const int* in_sizes, int n_in,
                              void* d_out, int out_size) {
    const float* X  = (const float*)d_in[0];
    const float* C0 = (const float*)d_in[1];
    int m = in_sizes[0] / NDIM;
    if (m > MAX_M) m = MAX_M;

    cudaFuncSetAttribute(assign_tc_kernel,
                         cudaFuncAttributeMaxDynamicSharedMemorySize,
                         ASSIGN_TC_SMEM);
    cudaFuncSetAttribute(accum_kernel,
                         cudaFuncAttributeMaxDynamicSharedMemorySize,
                         ACCUM_SMEM_BYTES);

    init_kernel<<<129, 128>>>(C0);
    xsq_kernel<<<(m + 7) / 8, 256>>>(X, m);

    int ablocks = (m + 127) / 128;
    for (int it = 0; it < MAXIT; ++it) {
        assign_tc_kernel<<<ablocks, 512, ASSIGN_TC_SMEM>>>(X, m);
        accum_kernel<<<NBLK_ACC, 384, ACCUM_SMEM_BYTES>>>(X, m);
        update_a_kernel<<<128, 1024>>>(it);
        update_b_kernel<<<128, 128>>>(it);
    }

    int fb = (out_size + 255) / 256;
    if (fb < 1) fb = 1;
    finalize_kernel<<<fb, 256>>>((float*)d_out, m, out_size);
}